// round 1
// baseline (speedup 1.0000x reference)
#include <cuda_runtime.h>

#define D_MODEL 1024
#define NHEAD   16
#define DEPTH   64
#define SEQ     2048
#define BATCH   4
#define MROWS   (BATCH*SEQ)   // 8192

// ---------------- scratch (device globals; no allocs allowed) ----------------
__device__ float g_qh[MROWS * D_MODEL];   // [B,H,S,DEPTH]
__device__ float g_kh[MROWS * D_MODEL];
__device__ float g_vh[MROWS * D_MODEL];
__device__ float g_attn[MROWS * D_MODEL]; // [B,S,D] flat

// ---------------- GEMM: Y = X @ W + bias, M=8192, N=K=1024 -------------------
// SPLIT=1: write head-split layout [B,H,S,DEPTH]; SPLIT=0: flat [M,N]
template <int SPLIT>
__global__ __launch_bounds__(256, 2)
void gemm_kernel(const float* __restrict__ X, const float* __restrict__ W,
                 const float* __restrict__ bias, float* __restrict__ Y)
{
    constexpr int BM = 128, BN = 128, BK = 8;
    constexpr int K = D_MODEL, N = D_MODEL;
    __shared__ float As[BK][BM];
    __shared__ float Bs[BK][BN];

    const int bx = blockIdx.x;   // N tile (0..7)
    const int by = blockIdx.y;   // M tile (0..63)
    const int tid = threadIdx.x;

    const int a_row = tid >> 1;          // 0..127
    const int a_col = (tid & 1) << 2;    // 0 or 4
    const int b_row = tid >> 5;          // 0..7
    const int b_col = (tid & 31) << 2;   // 0..124

    const int ty = tid >> 4;             // 0..15
    const int tx = tid & 15;             // 0..15

    const float* Ap = X + (size_t)(by * BM + a_row) * K + a_col;
    const float* Bp = W + (size_t)b_row * N + bx * BN + b_col;

    float acc[8][8];
#pragma unroll
    for (int i = 0; i < 8; i++)
#pragma unroll
        for (int j = 0; j < 8; j++) acc[i][j] = 0.f;

    for (int kt = 0; kt < K; kt += BK) {
        float4 av = *(const float4*)(Ap + kt);
        As[a_col + 0][a_row] = av.x;
        As[a_col + 1][a_row] = av.y;
        As[a_col + 2][a_row] = av.z;
        As[a_col + 3][a_row] = av.w;
        *(float4*)&Bs[b_row][b_col] = *(const float4*)(Bp + (size_t)kt * N);
        __syncthreads();

#pragma unroll
        for (int k = 0; k < BK; k++) {
            float a_f[8], b_f[8];
            *(float4*)&a_f[0] = *(float4*)&As[k][ty * 8];
            *(float4*)&a_f[4] = *(float4*)&As[k][ty * 8 + 4];
            *(float4*)&b_f[0] = *(float4*)&Bs[k][tx * 8];
            *(float4*)&b_f[4] = *(float4*)&Bs[k][tx * 8 + 4];
#pragma unroll
            for (int i = 0; i < 8; i++)
#pragma unroll
                for (int j = 0; j < 8; j++)
                    acc[i][j] += a_f[i] * b_f[j];
        }
        __syncthreads();
    }

    const int row0 = by * BM + ty * 8;
    const int col0 = bx * BN + tx * 8;
#pragma unroll
    for (int i = 0; i < 8; i++) {
        const int m = row0 + i;
#pragma unroll
        for (int jq = 0; jq < 2; jq++) {
            const int n = col0 + jq * 4;
            float4 v;
            v.x = acc[i][jq * 4 + 0] + bias[n + 0];
            v.y = acc[i][jq * 4 + 1] + bias[n + 1];
            v.z = acc[i][jq * 4 + 2] + bias[n + 2];
            v.w = acc[i][jq * 4 + 3] + bias[n + 3];
            if (SPLIT) {
                const int h = n >> 6, d = n & 63;
                const int b = m >> 11, s = m & (SEQ - 1);
                *(float4*)&Y[(size_t)(((b * NHEAD + h) * SEQ) + s) * DEPTH + d] = v;
            } else {
                *(float4*)&Y[(size_t)m * N + n] = v;
            }
        }
    }
}

// ---------------- Flash attention: per (b,h), 64-query tiles -----------------
#define BR 64
#define BC 64
#define KPITCH 66   // padded pitch for transposed K tile (kills STS conflicts)

__global__ __launch_bounds__(256, 2)
void attn_kernel(const float* __restrict__ Qh, const float* __restrict__ Kh,
                 const float* __restrict__ Vh, float* __restrict__ O)
{
    extern __shared__ float sm[];
    float* q_s = sm;                      // [64][64]
    float* k_s = sm + 64 * 64;            // [64][66]; aliased as P [8 warps][8][64]
    float* v_s = k_s + 64 * KPITCH;       // [64][64]

    const int qt = blockIdx.x;  // query tile (0..31)
    const int h  = blockIdx.y;
    const int b  = blockIdx.z;
    const int tid = threadIdx.x;
    const int w = tid >> 5;     // warp 0..7, owns rows w*8..w*8+7
    const int j = tid & 31;     // lane, owns cols 2j, 2j+1

    const float* Qbase = Qh + (size_t)(((b * NHEAD + h) * SEQ) + qt * BR) * DEPTH;
    const float* Kbase = Kh + (size_t)((b * NHEAD + h) * SEQ) * DEPTH;
    const float* Vbase = Vh + (size_t)((b * NHEAD + h) * SEQ) * DEPTH;

    // load Q tile (coalesced float4)
#pragma unroll
    for (int r = 0; r < 4; r++) {
        int idx4 = r * 256 + tid;
        *(float4*)&q_s[idx4 * 4] = *(const float4*)&Qbase[idx4 * 4];
    }

    float o0[8], o1[8], mrow[8], lrow[8];
#pragma unroll
    for (int i = 0; i < 8; i++) { o0[i] = 0.f; o1[i] = 0.f; mrow[i] = -1e30f; lrow[i] = 0.f; }

    float* p_w = k_s + w * (8 * BC);   // this warp's P region (aliases k_s)

#pragma unroll 1
    for (int kt = 0; kt < SEQ / BC; kt++) {
        __syncthreads();   // prior-iter v_s/P reads complete before overwrite

        // load K tile transposed: k_s[d][c]
        const float* Kt = Kbase + (size_t)kt * BC * DEPTH;
#pragma unroll
        for (int r = 0; r < 16; r++) {
            int idx = r * 256 + tid;
            int c = idx >> 6, d = idx & 63;
            k_s[d * KPITCH + c] = Kt[idx];
        }
        // load V tile: v_s[c][d]
        const float* Vt = Vbase + (size_t)kt * BC * DEPTH;
#pragma unroll
        for (int r = 0; r < 4; r++) {
            int idx4 = r * 256 + tid;
            *(float4*)&v_s[idx4 * 4] = *(const float4*)&Vt[idx4 * 4];
        }
        __syncthreads();

        // S = Q K^T : rows w*8..w*8+7, cols 2j, 2j+1
        float s0[8], s1[8];
#pragma unroll
        for (int i = 0; i < 8; i++) { s0[i] = 0.f; s1[i] = 0.f; }

#pragma unroll 4
        for (int d = 0; d < DEPTH; d += 4) {
            float2 k0 = *(const float2*)&k_s[(d + 0) * KPITCH + 2 * j];
            float2 k1 = *(const float2*)&k_s[(d + 1) * KPITCH + 2 * j];
            float2 k2 = *(const float2*)&k_s[(d + 2) * KPITCH + 2 * j];
            float2 k3 = *(const float2*)&k_s[(d + 3) * KPITCH + 2 * j];
#pragma unroll
            for (int i = 0; i < 8; i++) {
                float4 qv = *(const float4*)&q_s[(w * 8 + i) * DEPTH + d];
                s0[i] += qv.x * k0.x + qv.y * k1.x + qv.z * k2.x + qv.w * k3.x;
                s1[i] += qv.x * k0.y + qv.y * k1.y + qv.z * k2.y + qv.w * k3.y;
            }
        }

        __syncthreads();   // all warps done reading k_s before P overwrites it

        // online softmax per row; write P into aliased region
#pragma unroll
        for (int i = 0; i < 8; i++) {
            float a  = s0[i] * 0.125f;
            float c2 = s1[i] * 0.125f;
            float mx = fmaxf(a, c2);
#pragma unroll
            for (int off = 16; off; off >>= 1)
                mx = fmaxf(mx, __shfl_xor_sync(0xffffffffu, mx, off));
            float mnew = fmaxf(mrow[i], mx);
            float corr = __expf(mrow[i] - mnew);
            float p0 = __expf(a  - mnew);
            float p1 = __expf(c2 - mnew);
            float ssum = p0 + p1;
#pragma unroll
            for (int off = 16; off; off >>= 1)
                ssum += __shfl_xor_sync(0xffffffffu, ssum, off);
            lrow[i] = lrow[i] * corr + ssum;
            mrow[i] = mnew;
            o0[i] *= corr;
            o1[i] *= corr;
            float2 pv; pv.x = p0; pv.y = p1;
            *(float2*)&p_w[i * BC + 2 * j] = pv;
        }
        __syncwarp();

        // O += P V  (warp-private P, shared V)
#pragma unroll 4
        for (int c = 0; c < BC; c += 2) {
            float2 va = *(const float2*)&v_s[(c + 0) * DEPTH + 2 * j];
            float2 vb = *(const float2*)&v_s[(c + 1) * DEPTH + 2 * j];
#pragma unroll
            for (int i = 0; i < 8; i++) {
                float2 p = *(const float2*)&p_w[i * BC + c];
                o0[i] += p.x * va.x + p.y * vb.x;
                o1[i] += p.x * va.y + p.y * vb.y;
            }
        }
        __syncwarp();
    }

    // epilogue: normalize and write [B,S,D] flat
#pragma unroll
    for (int i = 0; i < 8; i++) {
        float inv = 1.0f / lrow[i];
        int row = qt * BR + w * 8 + i;
        float2 out; out.x = o0[i] * inv; out.y = o1[i] * inv;
        *(float2*)&O[(size_t)(b * SEQ + row) * D_MODEL + h * DEPTH + 2 * j] = out;
    }
}

// ---------------- launch -----------------------------------------------------
extern "C" void kernel_launch(void* const* d_in, const int* in_sizes, int n_in,
                              void* d_out, int out_size)
{
    const float* v  = (const float*)d_in[0];
    const float* k  = (const float*)d_in[1];
    const float* q  = (const float*)d_in[2];
    const float* wq = (const float*)d_in[3];
    const float* bq = (const float*)d_in[4];
    const float* wk = (const float*)d_in[5];
    const float* bk = (const float*)d_in[6];
    const float* wv = (const float*)d_in[7];
    const float* bv = (const float*)d_in[8];
    const float* wo = (const float*)d_in[9];
    const float* bo = (const float*)d_in[10];
    float* out = (float*)d_out;

    float *p_qh, *p_kh, *p_vh, *p_attn;
    cudaGetSymbolAddress((void**)&p_qh,   g_qh);
    cudaGetSymbolAddress((void**)&p_kh,   g_kh);
    cudaGetSymbolAddress((void**)&p_vh,   g_vh);
    cudaGetSymbolAddress((void**)&p_attn, g_attn);

    const int smem = (64 * 64 + 64 * KPITCH + 64 * 64) * (int)sizeof(float); // 49664
    cudaFuncSetAttribute(attn_kernel, cudaFuncAttributeMaxDynamicSharedMemorySize, smem);

    dim3 ggrid(D_MODEL / 128, MROWS / 128);   // (8, 64)
    gemm_kernel<1><<<ggrid, 256>>>(q, wq, bq, p_qh);
    gemm_kernel<1><<<ggrid, 256>>>(k, wk, bk, p_kh);
    gemm_kernel<1><<<ggrid, 256>>>(v, wv, bv, p_vh);

    dim3 agrid(SEQ / BR, NHEAD, BATCH);       // (32, 16, 4)
    attn_kernel<<<agrid, 256, smem>>>(p_qh, p_kh, p_vh, p_attn);

    gemm_kernel<0><<<ggrid, 256>>>(p_attn, wo, bo, out);
}

// round 3
// speedup vs baseline: 1.4573x; 1.4573x over previous
#include <cuda_runtime.h>
#include <cstdint>

#define D_MODEL 1024
#define NHEAD   16
#define DEPTH   64
#define SEQ     2048
#define BATCH   4
#define MROWS   (BATCH*SEQ)   // 8192

// ---------------- scratch (device globals; no allocs allowed) ----------------
__device__ float g_qh[MROWS * D_MODEL];   // [B,H,S,DEPTH]
__device__ float g_kh[MROWS * D_MODEL];
__device__ float g_vh[MROWS * D_MODEL];
__device__ float g_attn[MROWS * D_MODEL]; // [B,S,D] flat (tf32-rounded)
__device__ float g_qr[MROWS * D_MODEL];   // tf32-rounded activations
__device__ float g_kr[MROWS * D_MODEL];
__device__ float g_vr[MROWS * D_MODEL];
__device__ float g_wrq[D_MODEL * D_MODEL]; // tf32-rounded weights [K][N]
__device__ float g_wrk[D_MODEL * D_MODEL];
__device__ float g_wrv[D_MODEL * D_MODEL];
__device__ float g_wro[D_MODEL * D_MODEL];

// ---------------- helpers -----------------------------------------------------
__device__ __forceinline__ uint32_t smem_u32(const void* p) {
    return (uint32_t)__cvta_generic_to_shared(p);
}
__device__ __forceinline__ float tf32_rn(float x) {
    float r;
    asm("cvt.rna.tf32.f32 %0, %1;" : "=f"(r) : "f"(x));
    return r;
}
__device__ __forceinline__ void cp_async16(uint32_t dst, const void* src) {
    asm volatile("cp.async.cg.shared.global [%0], [%1], 16;" :: "r"(dst), "l"(src));
}
__device__ __forceinline__ void mma_tf32(float* c, const uint32_t* a, const uint32_t* b) {
    asm volatile(
        "mma.sync.aligned.m16n8k8.row.col.f32.tf32.tf32.f32 "
        "{%0,%1,%2,%3},{%4,%5,%6,%7},{%8,%9},{%0,%1,%2,%3};"
        : "+f"(c[0]), "+f"(c[1]), "+f"(c[2]), "+f"(c[3])
        : "r"(a[0]), "r"(a[1]), "r"(a[2]), "r"(a[3]), "r"(b[0]), "r"(b[1]));
}

// ---------------- prep: round fp32 -> tf32(rna) -------------------------------
__global__ void round_kernel(const float* __restrict__ X, float* __restrict__ Y)
{
    const int i = (blockIdx.x * 256 + threadIdx.x) * 4;
    float4 v = *(const float4*)(X + i);
    v.x = tf32_rn(v.x); v.y = tf32_rn(v.y); v.z = tf32_rn(v.z); v.w = tf32_rn(v.w);
    *(float4*)(Y + i) = v;
}

// ---------------- tf32 mma.sync GEMM ------------------------------------------
// Y[M=8192,N=1024] = A[M,K=1024] @ W[K,N] + bias
// split=1: write head-split [B,H,S,DEPTH]; split=0: flat [M,N]
#define APITCH 36    // floats, As[128][36]
#define BPITCH 136   // floats, Bs[32][136]
#define A_BUF  (128 * APITCH)
#define B_BUF  (32 * BPITCH)
#define GEMM_SMEM ((2 * A_BUF + 2 * B_BUF) * 4)   // 71680 B

__global__ __launch_bounds__(256, 2)
void mma_gemm(const float* __restrict__ A, const float* __restrict__ W,
              const float* __restrict__ bias, float* __restrict__ Y, int split)
{
    extern __shared__ float sm[];
    float* AsF = sm;                 // [2][128][36]
    float* BsF = sm + 2 * A_BUF;     // [2][32][136]
    const uint32_t sA = smem_u32(AsF);
    const uint32_t sB = smem_u32(BsF);

    const int tid  = threadIdx.x;
    const int wid  = tid >> 5, lane = tid & 31;
    const int gid  = lane >> 2, tig = lane & 3;
    const int warp_m = wid & 1;         // 0..1 -> 64-row half
    const int warp_n = wid >> 1;        // 0..3 -> 32-col quarter
    const int m0 = blockIdx.y * 128;
    const int n0 = blockIdx.x * 128;

    float acc[4][4][4];
#pragma unroll
    for (int mi = 0; mi < 4; mi++)
#pragma unroll
        for (int ni = 0; ni < 4; ni++)
#pragma unroll
            for (int r = 0; r < 4; r++) acc[mi][ni][r] = 0.f;

    auto fill = [&](int kt) {
        const int buf = kt & 1;
        const uint32_t dA = sA + buf * A_BUF * 4;
        const uint32_t dB = sB + buf * B_BUF * 4;
        const float* gA = A + (size_t)m0 * D_MODEL + kt * 32;
        const float* gB = W + (size_t)kt * 32 * D_MODEL + n0;
#pragma unroll
        for (int i = 0; i < 4; i++) {
            const int f = i * 256 + tid;
            const int ra = f >> 3, ca = (f & 7) * 4;          // A: 128 rows x 8 f4
            cp_async16(dA + (ra * APITCH + ca) * 4, gA + (size_t)ra * D_MODEL + ca);
            const int rb = f >> 5, cb = (f & 31) * 4;         // B: 32 rows x 32 f4
            cp_async16(dB + (rb * BPITCH + cb) * 4, gB + (size_t)rb * D_MODEL + cb);
        }
        asm volatile("cp.async.commit_group;");
    };

    auto compute = [&](int kt) {
        const int buf = kt & 1;
        const float* a_s = AsF + buf * A_BUF;
        const float* b_s = BsF + buf * B_BUF;
#pragma unroll
        for (int ks = 0; ks < 4; ks++) {
            const int k0 = ks * 8;
            uint32_t af[4][4], bf[4][2];
#pragma unroll
            for (int mi = 0; mi < 4; mi++) {
                const int r = warp_m * 64 + mi * 16 + gid;
                af[mi][0] = __float_as_uint(a_s[r * APITCH + k0 + tig]);
                af[mi][1] = __float_as_uint(a_s[(r + 8) * APITCH + k0 + tig]);
                af[mi][2] = __float_as_uint(a_s[r * APITCH + k0 + tig + 4]);
                af[mi][3] = __float_as_uint(a_s[(r + 8) * APITCH + k0 + tig + 4]);
            }
#pragma unroll
            for (int ni = 0; ni < 4; ni++) {
                const int c = warp_n * 32 + ni * 8 + gid;
                bf[ni][0] = __float_as_uint(b_s[(k0 + tig) * BPITCH + c]);
                bf[ni][1] = __float_as_uint(b_s[(k0 + tig + 4) * BPITCH + c]);
            }
#pragma unroll
            for (int mi = 0; mi < 4; mi++)
#pragma unroll
                for (int ni = 0; ni < 4; ni++)
                    mma_tf32(acc[mi][ni], af[mi], bf[ni]);
        }
    };

    fill(0);
    fill(1);
    asm volatile("cp.async.wait_group 1;");
    __syncthreads();

#pragma unroll 1
    for (int kt = 0; kt < 32; kt++) {
        compute(kt);
        __syncthreads();
        if (kt + 2 < 32) {
            fill(kt + 2);
            asm volatile("cp.async.wait_group 1;");
        } else {
            asm volatile("cp.async.wait_group 0;");
        }
        __syncthreads();
    }

    // epilogue
#pragma unroll
    for (int mi = 0; mi < 4; mi++) {
        const int r = m0 + warp_m * 64 + mi * 16 + gid;
#pragma unroll
        for (int ni = 0; ni < 4; ni++) {
            const int n = n0 + warp_n * 32 + ni * 8 + 2 * tig;
            const float bv0 = bias[n], bv1 = bias[n + 1];
            float2 lo, hi;
            lo.x = acc[mi][ni][0] + bv0; lo.y = acc[mi][ni][1] + bv1;
            hi.x = acc[mi][ni][2] + bv0; hi.y = acc[mi][ni][3] + bv1;
            if (split) {
                const int h = n >> 6, d = n & 63;
                const int b0 = r >> 11, s0 = r & (SEQ - 1);
                const int b1 = (r + 8) >> 11, s1 = (r + 8) & (SEQ - 1);
                *(float2*)&Y[(size_t)(((b0 * NHEAD + h) * SEQ) + s0) * DEPTH + d] = lo;
                *(float2*)&Y[(size_t)(((b1 * NHEAD + h) * SEQ) + s1) * DEPTH + d] = hi;
            } else {
                *(float2*)&Y[(size_t)r * D_MODEL + n] = lo;
                *(float2*)&Y[(size_t)(r + 8) * D_MODEL + n] = hi;
            }
        }
    }
}

// ---------------- Flash attention (fp32) --------------------------------------
#define BR 64
#define BC 64
#define KPITCH 66

__global__ __launch_bounds__(256, 2)
void attn_kernel(const float* __restrict__ Qh, const float* __restrict__ Kh,
                 const float* __restrict__ Vh, float* __restrict__ O)
{
    extern __shared__ float smf[];
    float* q_s = smf;
    float* k_s = smf + 64 * 64;
    float* v_s = k_s + 64 * KPITCH;

    const int qt = blockIdx.x;
    const int h  = blockIdx.y;
    const int b  = blockIdx.z;
    const int tid = threadIdx.x;
    const int w = tid >> 5;
    const int j = tid & 31;

    const float* Qbase = Qh + (size_t)(((b * NHEAD + h) * SEQ) + qt * BR) * DEPTH;
    const float* Kbase = Kh + (size_t)((b * NHEAD + h) * SEQ) * DEPTH;
    const float* Vbase = Vh + (size_t)((b * NHEAD + h) * SEQ) * DEPTH;

#pragma unroll
    for (int r = 0; r < 4; r++) {
        int idx4 = r * 256 + tid;
        *(float4*)&q_s[idx4 * 4] = *(const float4*)&Qbase[idx4 * 4];
    }

    float o0[8], o1[8], mrow[8], lrow[8];
#pragma unroll
    for (int i = 0; i < 8; i++) { o0[i] = 0.f; o1[i] = 0.f; mrow[i] = -1e30f; lrow[i] = 0.f; }

    float* p_w = k_s + w * (8 * BC);

#pragma unroll 1
    for (int kt = 0; kt < SEQ / BC; kt++) {
        __syncthreads();

        const float* Kt = Kbase + (size_t)kt * BC * DEPTH;
#pragma unroll
        for (int r = 0; r < 16; r++) {
            int idx = r * 256 + tid;
            int c = idx >> 6, d = idx & 63;
            k_s[d * KPITCH + c] = Kt[idx];
        }
        const float* Vt = Vbase + (size_t)kt * BC * DEPTH;
#pragma unroll
        for (int r = 0; r < 4; r++) {
            int idx4 = r * 256 + tid;
            *(float4*)&v_s[idx4 * 4] = *(const float4*)&Vt[idx4 * 4];
        }
        __syncthreads();

        float s0[8], s1[8];
#pragma unroll
        for (int i = 0; i < 8; i++) { s0[i] = 0.f; s1[i] = 0.f; }

#pragma unroll 4
        for (int d = 0; d < DEPTH; d += 4) {
            float2 k0 = *(const float2*)&k_s[(d + 0) * KPITCH + 2 * j];
            float2 k1 = *(const float2*)&k_s[(d + 1) * KPITCH + 2 * j];
            float2 k2 = *(const float2*)&k_s[(d + 2) * KPITCH + 2 * j];
            float2 k3 = *(const float2*)&k_s[(d + 3) * KPITCH + 2 * j];
#pragma unroll
            for (int i = 0; i < 8; i++) {
                float4 qv = *(const float4*)&q_s[(w * 8 + i) * DEPTH + d];
                s0[i] += qv.x * k0.x + qv.y * k1.x + qv.z * k2.x + qv.w * k3.x;
                s1[i] += qv.x * k0.y + qv.y * k1.y + qv.z * k2.y + qv.w * k3.y;
            }
        }

        __syncthreads();

#pragma unroll
        for (int i = 0; i < 8; i++) {
            float a  = s0[i] * 0.125f;
            float c2 = s1[i] * 0.125f;
            float mx = fmaxf(a, c2);
#pragma unroll
            for (int off = 16; off; off >>= 1)
                mx = fmaxf(mx, __shfl_xor_sync(0xffffffffu, mx, off));
            float mnew = fmaxf(mrow[i], mx);
            float corr = __expf(mrow[i] - mnew);
            float p0 = __expf(a  - mnew);
            float p1 = __expf(c2 - mnew);
            float ssum = p0 + p1;
#pragma unroll
            for (int off = 16; off; off >>= 1)
                ssum += __shfl_xor_sync(0xffffffffu, ssum, off);
            lrow[i] = lrow[i] * corr + ssum;
            mrow[i] = mnew;
            o0[i] *= corr;
            o1[i] *= corr;
            float2 pv; pv.x = p0; pv.y = p1;
            *(float2*)&p_w[i * BC + 2 * j] = pv;
        }
        __syncwarp();

#pragma unroll 4
        for (int c = 0; c < BC; c += 2) {
            float2 va = *(const float2*)&v_s[(c + 0) * DEPTH + 2 * j];
            float2 vb = *(const float2*)&v_s[(c + 1) * DEPTH + 2 * j];
#pragma unroll
            for (int i = 0; i < 8; i++) {
                float2 p = *(const float2*)&p_w[i * BC + c];
                o0[i] += p.x * va.x + p.y * vb.x;
                o1[i] += p.x * va.y + p.y * vb.y;
            }
        }
        __syncwarp();
    }

#pragma unroll
    for (int i = 0; i < 8; i++) {
        float inv = 1.0f / lrow[i];
        int row = qt * BR + w * 8 + i;
        float2 out;
        out.x = tf32_rn(o0[i] * inv);   // pre-round for the tf32 output projection
        out.y = tf32_rn(o1[i] * inv);
        *(float2*)&O[(size_t)(b * SEQ + row) * D_MODEL + h * DEPTH + 2 * j] = out;
    }
}

// ---------------- launch -------------------------------------------------------
extern "C" void kernel_launch(void* const* d_in, const int* in_sizes, int n_in,
                              void* d_out, int out_size)
{
    const float* v  = (const float*)d_in[0];
    const float* k  = (const float*)d_in[1];
    const float* q  = (const float*)d_in[2];
    const float* wq = (const float*)d_in[3];
    const float* bq = (const float*)d_in[4];
    const float* wk = (const float*)d_in[5];
    const float* bk = (const float*)d_in[6];
    const float* wv = (const float*)d_in[7];
    const float* bv = (const float*)d_in[8];
    const float* wo = (const float*)d_in[9];
    const float* bo = (const float*)d_in[10];
    float* out = (float*)d_out;

    float *p_qh, *p_kh, *p_vh, *p_attn, *p_qr, *p_kr, *p_vr;
    float *p_wrq, *p_wrk, *p_wrv, *p_wro;
    cudaGetSymbolAddress((void**)&p_qh,   g_qh);
    cudaGetSymbolAddress((void**)&p_kh,   g_kh);
    cudaGetSymbolAddress((void**)&p_vh,   g_vh);
    cudaGetSymbolAddress((void**)&p_attn, g_attn);
    cudaGetSymbolAddress((void**)&p_qr,   g_qr);
    cudaGetSymbolAddress((void**)&p_kr,   g_kr);
    cudaGetSymbolAddress((void**)&p_vr,   g_vr);
    cudaGetSymbolAddress((void**)&p_wrq,  g_wrq);
    cudaGetSymbolAddress((void**)&p_wrk,  g_wrk);
    cudaGetSymbolAddress((void**)&p_wrv,  g_wrv);
    cudaGetSymbolAddress((void**)&p_wro,  g_wro);

    cudaFuncSetAttribute(mma_gemm, cudaFuncAttributeMaxDynamicSharedMemorySize, GEMM_SMEM);
    const int attn_smem = (64 * 64 + 64 * KPITCH + 64 * 64) * (int)sizeof(float);
    cudaFuncSetAttribute(attn_kernel, cudaFuncAttributeMaxDynamicSharedMemorySize, attn_smem);

    // prep: round weights + activations to tf32-representable values
    const int rblocks_act = (MROWS * D_MODEL) / (256 * 4);    // 8192 blocks
    const int rblocks_w   = (D_MODEL * D_MODEL) / (256 * 4);  // 1024 blocks
    round_kernel<<<rblocks_act, 256>>>(q, p_qr);
    round_kernel<<<rblocks_act, 256>>>(k, p_kr);
    round_kernel<<<rblocks_act, 256>>>(v, p_vr);
    round_kernel<<<rblocks_w, 256>>>(wq, p_wrq);
    round_kernel<<<rblocks_w, 256>>>(wk, p_wrk);
    round_kernel<<<rblocks_w, 256>>>(wv, p_wrv);
    round_kernel<<<rblocks_w, 256>>>(wo, p_wro);

    // projections (tensor-core tf32)
    dim3 ggrid(D_MODEL / 128, MROWS / 128);   // (8, 64)
    mma_gemm<<<ggrid, 256, GEMM_SMEM>>>(p_qr, p_wrq, bq, p_qh, 1);
    mma_gemm<<<ggrid, 256, GEMM_SMEM>>>(p_kr, p_wrk, bk, p_kh, 1);
    mma_gemm<<<ggrid, 256, GEMM_SMEM>>>(p_vr, p_wrv, bv, p_vh, 1);

    // attention (fp32)
    dim3 agrid(SEQ / BR, NHEAD, BATCH);
    attn_kernel<<<agrid, 256, attn_smem>>>(p_qh, p_kh, p_vh, p_attn);

    // output projection (tensor-core tf32)
    mma_gemm<<<ggrid, 256, GEMM_SMEM>>>(p_attn, p_wro, bo, out, 0);
}

// round 4
// speedup vs baseline: 2.4638x; 1.6907x over previous
#include <cuda_runtime.h>
#include <cstdint>

#define D_MODEL 1024
#define NHEAD   16
#define DEPTH   64
#define SEQ     2048
#define BATCH   4
#define MROWS   (BATCH*SEQ)   // 8192

// ---------------- scratch (device globals; no allocs allowed) ----------------
__device__ float g_qh[MROWS * D_MODEL];   // [B,H,S,DEPTH]
__device__ float g_kh[MROWS * D_MODEL];
__device__ float g_vh[MROWS * D_MODEL];
__device__ float g_attn[MROWS * D_MODEL]; // [B,S,D] flat (raw fp32)
__device__ float g_wrq[D_MODEL * D_MODEL]; // tf32-rounded weights [K][N]
__device__ float g_wrk[D_MODEL * D_MODEL];
__device__ float g_wrv[D_MODEL * D_MODEL];
__device__ float g_wro[D_MODEL * D_MODEL];

// ---------------- helpers -----------------------------------------------------
__device__ __forceinline__ uint32_t smem_u32(const void* p) {
    return (uint32_t)__cvta_generic_to_shared(p);
}
__device__ __forceinline__ float tf32_rn(float x) {
    float r;
    asm("cvt.rna.tf32.f32 %0, %1;" : "=f"(r) : "f"(x));
    return r;
}
__device__ __forceinline__ void cp_async16(uint32_t dst, const void* src) {
    asm volatile("cp.async.cg.shared.global [%0], [%1], 16;" :: "r"(dst), "l"(src));
}
__device__ __forceinline__ void mma_tf32(float* c, const uint32_t* a, const uint32_t* b) {
    asm volatile(
        "mma.sync.aligned.m16n8k8.row.col.f32.tf32.tf32.f32 "
        "{%0,%1,%2,%3},{%4,%5,%6,%7},{%8,%9},{%0,%1,%2,%3};"
        : "+f"(c[0]), "+f"(c[1]), "+f"(c[2]), "+f"(c[3])
        : "r"(a[0]), "r"(a[1]), "r"(a[2]), "r"(a[3]), "r"(b[0]), "r"(b[1]));
}

// ---------------- prep: round weights fp32 -> tf32(rna) -----------------------
__global__ void round_kernel(const float* __restrict__ X, float* __restrict__ Y)
{
    const int i = (blockIdx.x * 256 + threadIdx.x) * 4;
    float4 v = *(const float4*)(X + i);
    v.x = tf32_rn(v.x); v.y = tf32_rn(v.y); v.z = tf32_rn(v.z); v.w = tf32_rn(v.w);
    *(float4*)(Y + i) = v;
}

// ---------------- tf32 mma.sync GEMM, A-operand 2-term split -------------------
// Y[M=8192,N=1024] = A[M,K=1024] @ W[K,N] + bias   (A raw fp32, W tf32-rounded)
// split=1: write head-split [B,H,S,DEPTH]; split=0: flat [M,N]
#define APITCH 36    // floats, As[128][36]
#define BPITCH 136   // floats, Bs[32][136]
#define A_BUF  (128 * APITCH)
#define B_BUF  (32 * BPITCH)
#define GEMM_SMEM ((2 * A_BUF + 2 * B_BUF) * 4)   // 71680 B

__global__ __launch_bounds__(256, 2)
void mma_gemm(const float* __restrict__ A, const float* __restrict__ W,
              const float* __restrict__ bias, float* __restrict__ Y, int split)
{
    extern __shared__ float sm[];
    float* AsF = sm;                 // [2][128][36]
    float* BsF = sm + 2 * A_BUF;     // [2][32][136]
    const uint32_t sA = smem_u32(AsF);
    const uint32_t sB = smem_u32(BsF);

    const int tid  = threadIdx.x;
    const int wid  = tid >> 5, lane = tid & 31;
    const int gid  = lane >> 2, tig = lane & 3;
    const int warp_m = wid & 1;
    const int warp_n = wid >> 1;
    const int m0 = blockIdx.y * 128;
    const int n0 = blockIdx.x * 128;

    float acc[4][4][4];
#pragma unroll
    for (int mi = 0; mi < 4; mi++)
#pragma unroll
        for (int ni = 0; ni < 4; ni++)
#pragma unroll
            for (int r = 0; r < 4; r++) acc[mi][ni][r] = 0.f;

    auto fill = [&](int kt) {
        const int buf = kt & 1;
        const uint32_t dA = sA + buf * A_BUF * 4;
        const uint32_t dB = sB + buf * B_BUF * 4;
        const float* gA = A + (size_t)m0 * D_MODEL + kt * 32;
        const float* gB = W + (size_t)kt * 32 * D_MODEL + n0;
#pragma unroll
        for (int i = 0; i < 4; i++) {
            const int f = i * 256 + tid;
            const int ra = f >> 3, ca = (f & 7) * 4;
            cp_async16(dA + (ra * APITCH + ca) * 4, gA + (size_t)ra * D_MODEL + ca);
            const int rb = f >> 5, cb = (f & 31) * 4;
            cp_async16(dB + (rb * BPITCH + cb) * 4, gB + (size_t)rb * D_MODEL + cb);
        }
        asm volatile("cp.async.commit_group;");
    };

    auto compute = [&](int kt) {
        const int buf = kt & 1;
        const float* a_s = AsF + buf * A_BUF;
        const float* b_s = BsF + buf * B_BUF;
#pragma unroll
        for (int ks = 0; ks < 4; ks++) {
            const int k0 = ks * 8;
            uint32_t ah[4][4], al[4][4], bf[4][2];
#pragma unroll
            for (int mi = 0; mi < 4; mi++) {
                const int r = warp_m * 64 + mi * 16 + gid;
                float f0 = a_s[r * APITCH + k0 + tig];
                float f1 = a_s[(r + 8) * APITCH + k0 + tig];
                float f2 = a_s[r * APITCH + k0 + tig + 4];
                float f3 = a_s[(r + 8) * APITCH + k0 + tig + 4];
                float h0 = tf32_rn(f0), h1 = tf32_rn(f1);
                float h2 = tf32_rn(f2), h3 = tf32_rn(f3);
                ah[mi][0] = __float_as_uint(h0); al[mi][0] = __float_as_uint(tf32_rn(f0 - h0));
                ah[mi][1] = __float_as_uint(h1); al[mi][1] = __float_as_uint(tf32_rn(f1 - h1));
                ah[mi][2] = __float_as_uint(h2); al[mi][2] = __float_as_uint(tf32_rn(f2 - h2));
                ah[mi][3] = __float_as_uint(h3); al[mi][3] = __float_as_uint(tf32_rn(f3 - h3));
            }
#pragma unroll
            for (int ni = 0; ni < 4; ni++) {
                const int c = warp_n * 32 + ni * 8 + gid;
                bf[ni][0] = __float_as_uint(b_s[(k0 + tig) * BPITCH + c]);
                bf[ni][1] = __float_as_uint(b_s[(k0 + tig + 4) * BPITCH + c]);
            }
#pragma unroll
            for (int mi = 0; mi < 4; mi++)
#pragma unroll
                for (int ni = 0; ni < 4; ni++) {
                    mma_tf32(acc[mi][ni], ah[mi], bf[ni]);
                    mma_tf32(acc[mi][ni], al[mi], bf[ni]);
                }
        }
    };

    fill(0);
    fill(1);
    asm volatile("cp.async.wait_group 1;");
    __syncthreads();

#pragma unroll 1
    for (int kt = 0; kt < 32; kt++) {
        compute(kt);
        __syncthreads();
        if (kt + 2 < 32) {
            fill(kt + 2);
            asm volatile("cp.async.wait_group 1;");
        } else {
            asm volatile("cp.async.wait_group 0;");
        }
        __syncthreads();
    }

#pragma unroll
    for (int mi = 0; mi < 4; mi++) {
        const int r = m0 + warp_m * 64 + mi * 16 + gid;
#pragma unroll
        for (int ni = 0; ni < 4; ni++) {
            const int n = n0 + warp_n * 32 + ni * 8 + 2 * tig;
            const float bv0 = bias[n], bv1 = bias[n + 1];
            float2 lo, hi;
            lo.x = acc[mi][ni][0] + bv0; lo.y = acc[mi][ni][1] + bv1;
            hi.x = acc[mi][ni][2] + bv0; hi.y = acc[mi][ni][3] + bv1;
            if (split) {
                const int h = n >> 6, d = n & 63;
                const int b0 = r >> 11, s0 = r & (SEQ - 1);
                const int b1 = (r + 8) >> 11, s1 = (r + 8) & (SEQ - 1);
                *(float2*)&Y[(size_t)(((b0 * NHEAD + h) * SEQ) + s0) * DEPTH + d] = lo;
                *(float2*)&Y[(size_t)(((b1 * NHEAD + h) * SEQ) + s1) * DEPTH + d] = hi;
            } else {
                *(float2*)&Y[(size_t)r * D_MODEL + n] = lo;
                *(float2*)&Y[(size_t)(r + 8) * D_MODEL + n] = hi;
            }
        }
    }
}

// ---------------- tensor-core flash attention ---------------------------------
// grid (SEQ/128, NHEAD, BATCH), 256 threads (8 warps), warp w owns rows 16w..16w+15
#define ABR 128
#define ABC 32
#define QP  68
#define KP  68
#define VP  72
#define ATTN_SMEM ((ABR*QP + 2*ABC*KP + 2*ABC*VP) * 4)   // 70656 B

__global__ __launch_bounds__(256, 2)
void attn_tc(const float* __restrict__ Qh, const float* __restrict__ Kh,
             const float* __restrict__ Vh, float* __restrict__ O)
{
    extern __shared__ float smf[];
    float* q_s = smf;                         // [128][68]
    float* k_s = smf + ABR * QP;              // [2][32][68]
    float* v_s = k_s + 2 * ABC * KP;          // [2][32][72]
    const uint32_t sK = smem_u32(k_s);
    const uint32_t sV = smem_u32(v_s);

    const int qt = blockIdx.x;
    const int h  = blockIdx.y;
    const int b  = blockIdx.z;
    const int tid = threadIdx.x;
    const int w = tid >> 5, lane = tid & 31;
    const int gid = lane >> 2, tig = lane & 3;

    const float* Qb = Qh + (size_t)(((b * NHEAD + h) * SEQ) + qt * ABR) * DEPTH;
    const float* Kb = Kh + (size_t)((b * NHEAD + h) * SEQ) * DEPTH;
    const float* Vb = Vh + (size_t)((b * NHEAD + h) * SEQ) * DEPTH;

    // load Q (scaled by 1/sqrt(depth)) into smem
#pragma unroll
    for (int i = 0; i < 8; i++) {
        const int f4 = i * 256 + tid;
        const int r = f4 >> 4, c = (f4 & 15) * 4;
        float4 qv = *(const float4*)(Qb + (size_t)r * DEPTH + c);
        qv.x *= 0.125f; qv.y *= 0.125f; qv.z *= 0.125f; qv.w *= 0.125f;
        *(float4*)&q_s[r * QP + c] = qv;
    }

    auto fill = [&](int kt) {
        const int buf = kt & 1;
        const float* gK = Kb + (size_t)kt * ABC * DEPTH;
        const float* gV = Vb + (size_t)kt * ABC * DEPTH;
#pragma unroll
        for (int i = 0; i < 2; i++) {
            const int f4 = i * 256 + tid;
            const int r = f4 >> 4, c = (f4 & 15) * 4;
            cp_async16(sK + (buf * ABC * KP + r * KP + c) * 4, gK + (size_t)r * DEPTH + c);
            cp_async16(sV + (buf * ABC * VP + r * VP + c) * 4, gV + (size_t)r * DEPTH + c);
        }
        asm volatile("cp.async.commit_group;");
    };

    float m0 = -1e30f, m1 = -1e30f, l0 = 0.f, l1 = 0.f;
    float o[8][4];
#pragma unroll
    for (int nt = 0; nt < 8; nt++)
#pragma unroll
        for (int r = 0; r < 4; r++) o[nt][r] = 0.f;

    fill(0);
    __syncthreads();   // also covers q_s stores vs first frag reads

#pragma unroll 1
    for (int kt = 0; kt < SEQ / ABC; kt++) {
        if (kt + 1 < SEQ / ABC) {
            fill(kt + 1);
            asm volatile("cp.async.wait_group 1;");
        } else {
            asm volatile("cp.async.wait_group 0;");
        }
        __syncthreads();

        const float* ks_ = k_s + (kt & 1) * ABC * KP;
        const float* vs_ = v_s + (kt & 1) * ABC * VP;

        // ---- S = Q K^T (Q 2-term split, K plain tf32) ----
        float s[4][4];
#pragma unroll
        for (int nt = 0; nt < 4; nt++)
#pragma unroll
            for (int r = 0; r < 4; r++) s[nt][r] = 0.f;

#pragma unroll
        for (int ks = 0; ks < 8; ks++) {
            const int k0 = ks * 8;
            const int qr = 16 * w + gid;
            float f0 = q_s[qr * QP + k0 + tig];
            float f1 = q_s[(qr + 8) * QP + k0 + tig];
            float f2 = q_s[qr * QP + k0 + tig + 4];
            float f3 = q_s[(qr + 8) * QP + k0 + tig + 4];
            float h0 = tf32_rn(f0), h1 = tf32_rn(f1), h2 = tf32_rn(f2), h3 = tf32_rn(f3);
            uint32_t ah[4] = {__float_as_uint(h0), __float_as_uint(h1),
                              __float_as_uint(h2), __float_as_uint(h3)};
            uint32_t al[4] = {__float_as_uint(tf32_rn(f0 - h0)), __float_as_uint(tf32_rn(f1 - h1)),
                              __float_as_uint(tf32_rn(f2 - h2)), __float_as_uint(tf32_rn(f3 - h3))};
#pragma unroll
            for (int nt = 0; nt < 4; nt++) {
                uint32_t bh[2];
                bh[0] = __float_as_uint(tf32_rn(ks_[(8 * nt + gid) * KP + k0 + tig]));
                bh[1] = __float_as_uint(tf32_rn(ks_[(8 * nt + gid) * KP + k0 + tig + 4]));
                mma_tf32(s[nt], ah, bh);
                mma_tf32(s[nt], al, bh);
            }
        }

        // ---- online softmax ----
        float smax0 = -1e30f, smax1 = -1e30f;
#pragma unroll
        for (int nt = 0; nt < 4; nt++) {
            smax0 = fmaxf(smax0, fmaxf(s[nt][0], s[nt][1]));
            smax1 = fmaxf(smax1, fmaxf(s[nt][2], s[nt][3]));
        }
#pragma unroll
        for (int off = 1; off <= 2; off <<= 1) {
            smax0 = fmaxf(smax0, __shfl_xor_sync(0xffffffffu, smax0, off));
            smax1 = fmaxf(smax1, __shfl_xor_sync(0xffffffffu, smax1, off));
        }
        const float mn0 = fmaxf(m0, smax0), mn1 = fmaxf(m1, smax1);
        const float cr0 = __expf(m0 - mn0), cr1 = __expf(m1 - mn1);
        float sum0 = 0.f, sum1 = 0.f;
#pragma unroll
        for (int nt = 0; nt < 4; nt++) {
            s[nt][0] = __expf(s[nt][0] - mn0);
            s[nt][1] = __expf(s[nt][1] - mn0);
            s[nt][2] = __expf(s[nt][2] - mn1);
            s[nt][3] = __expf(s[nt][3] - mn1);
            sum0 += s[nt][0] + s[nt][1];
            sum1 += s[nt][2] + s[nt][3];
        }
#pragma unroll
        for (int off = 1; off <= 2; off <<= 1) {
            sum0 += __shfl_xor_sync(0xffffffffu, sum0, off);
            sum1 += __shfl_xor_sync(0xffffffffu, sum1, off);
        }
        l0 = l0 * cr0 + sum0; l1 = l1 * cr1 + sum1;
        m0 = mn0; m1 = mn1;
#pragma unroll
        for (int nt = 0; nt < 8; nt++) {
            o[nt][0] *= cr0; o[nt][1] *= cr0;
            o[nt][2] *= cr1; o[nt][3] *= cr1;
        }

        // ---- O += P V (P A-fragments via quad shuffles) ----
        const int src1 = (lane & ~3) | (tig >> 1);
        const int src2 = src1 + 2;
        const bool odd = tig & 1;
#pragma unroll
        for (int kc = 0; kc < 4; kc++) {
            float x0 = __shfl_sync(0xffffffffu, s[kc][0], src1);
            float x1 = __shfl_sync(0xffffffffu, s[kc][1], src1);
            float x2 = __shfl_sync(0xffffffffu, s[kc][2], src1);
            float x3 = __shfl_sync(0xffffffffu, s[kc][3], src1);
            float y0 = __shfl_sync(0xffffffffu, s[kc][0], src2);
            float y1 = __shfl_sync(0xffffffffu, s[kc][1], src2);
            float y2 = __shfl_sync(0xffffffffu, s[kc][2], src2);
            float y3 = __shfl_sync(0xffffffffu, s[kc][3], src2);
            uint32_t ap[4];
            ap[0] = __float_as_uint(tf32_rn(odd ? x1 : x0));   // P[gid   ][8kc+tig  ]
            ap[1] = __float_as_uint(tf32_rn(odd ? x3 : x2));   // P[gid+8 ][8kc+tig  ]
            ap[2] = __float_as_uint(tf32_rn(odd ? y1 : y0));   // P[gid   ][8kc+tig+4]
            ap[3] = __float_as_uint(tf32_rn(odd ? y3 : y2));   // P[gid+8 ][8kc+tig+4]
#pragma unroll
            for (int nt = 0; nt < 8; nt++) {
                uint32_t bv[2];
                bv[0] = __float_as_uint(tf32_rn(vs_[(8 * kc + tig) * VP + 8 * nt + gid]));
                bv[1] = __float_as_uint(tf32_rn(vs_[(8 * kc + tig + 4) * VP + 8 * nt + gid]));
                mma_tf32(o[nt], ap, bv);
            }
        }
        __syncthreads();   // done reading this buffer before it is refilled
    }

    // epilogue: normalize, write [B,S,D] flat (raw fp32; output proj splits A itself)
    const float inv0 = 1.f / l0, inv1 = 1.f / l1;
    const int r0 = qt * ABR + 16 * w + gid;
    const int r1 = r0 + 8;
#pragma unroll
    for (int nt = 0; nt < 8; nt++) {
        const int d = h * DEPTH + 8 * nt + 2 * tig;
        float2 lo, hi;
        lo.x = o[nt][0] * inv0; lo.y = o[nt][1] * inv0;
        hi.x = o[nt][2] * inv1; hi.y = o[nt][3] * inv1;
        *(float2*)&O[(size_t)(b * SEQ + r0) * D_MODEL + d] = lo;
        *(float2*)&O[(size_t)(b * SEQ + r1) * D_MODEL + d] = hi;
    }
}

// ---------------- launch -------------------------------------------------------
extern "C" void kernel_launch(void* const* d_in, const int* in_sizes, int n_in,
                              void* d_out, int out_size)
{
    const float* v  = (const float*)d_in[0];
    const float* k  = (const float*)d_in[1];
    const float* q  = (const float*)d_in[2];
    const float* wq = (const float*)d_in[3];
    const float* bq = (const float*)d_in[4];
    const float* wk = (const float*)d_in[5];
    const float* bk = (const float*)d_in[6];
    const float* wv = (const float*)d_in[7];
    const float* bv = (const float*)d_in[8];
    const float* wo = (const float*)d_in[9];
    const float* bo = (const float*)d_in[10];
    float* out = (float*)d_out;

    float *p_qh, *p_kh, *p_vh, *p_attn;
    float *p_wrq, *p_wrk, *p_wrv, *p_wro;
    cudaGetSymbolAddress((void**)&p_qh,   g_qh);
    cudaGetSymbolAddress((void**)&p_kh,   g_kh);
    cudaGetSymbolAddress((void**)&p_vh,   g_vh);
    cudaGetSymbolAddress((void**)&p_attn, g_attn);
    cudaGetSymbolAddress((void**)&p_wrq,  g_wrq);
    cudaGetSymbolAddress((void**)&p_wrk,  g_wrk);
    cudaGetSymbolAddress((void**)&p_wrv,  g_wrv);
    cudaGetSymbolAddress((void**)&p_wro,  g_wro);

    cudaFuncSetAttribute(mma_gemm, cudaFuncAttributeMaxDynamicSharedMemorySize, GEMM_SMEM);
    cudaFuncSetAttribute(attn_tc,  cudaFuncAttributeMaxDynamicSharedMemorySize, ATTN_SMEM);

    // prep: round weights to tf32-representable values
    const int rblocks_w = (D_MODEL * D_MODEL) / (256 * 4);
    round_kernel<<<rblocks_w, 256>>>(wq, p_wrq);
    round_kernel<<<rblocks_w, 256>>>(wk, p_wrk);
    round_kernel<<<rblocks_w, 256>>>(wv, p_wrv);
    round_kernel<<<rblocks_w, 256>>>(wo, p_wro);

    // projections (tf32 tensor, A-split; raw activations)
    dim3 ggrid(D_MODEL / 128, MROWS / 128);   // (8, 64)
    mma_gemm<<<ggrid, 256, GEMM_SMEM>>>(q, p_wrq, bq, p_qh, 1);
    mma_gemm<<<ggrid, 256, GEMM_SMEM>>>(k, p_wrk, bk, p_kh, 1);
    mma_gemm<<<ggrid, 256, GEMM_SMEM>>>(v, p_wrv, bv, p_vh, 1);

    // attention (tf32 tensor, flash)
    dim3 agrid(SEQ / ABR, NHEAD, BATCH);      // (16, 16, 4)
    attn_tc<<<agrid, 256, ATTN_SMEM>>>(p_qh, p_kh, p_vh, p_attn);

    // output projection
    mma_gemm<<<ggrid, 256, GEMM_SMEM>>>(p_attn, p_wro, bo, out, 0);
}

// round 6
// speedup vs baseline: 3.3334x; 1.3529x over previous
#include <cuda_runtime.h>
#include <cstdint>

#define D_MODEL 1024
#define NHEAD   16
#define DEPTH   64
#define SEQ     2048
#define BATCH   4
#define MROWS   (BATCH*SEQ)   // 8192

// ---------------- scratch (device globals; no allocs allowed) ----------------
__device__ float g_qh[MROWS * D_MODEL];   // [B,H,S,DEPTH] raw fp32 (for Q-split)
__device__ float g_kh[MROWS * D_MODEL];   // [B,H,S,DEPTH] tf32-rounded
__device__ float g_vh[MROWS * D_MODEL];   // [B,H,S,DEPTH] tf32-rounded
__device__ float g_attn[MROWS * D_MODEL]; // [B,S,D] flat, tf32-rounded
__device__ float g_qr[MROWS * D_MODEL];   // tf32-rounded activations
__device__ float g_kr[MROWS * D_MODEL];
__device__ float g_vr[MROWS * D_MODEL];
__device__ float g_wrq[D_MODEL * D_MODEL]; // tf32-rounded weights [K][N]
__device__ float g_wrk[D_MODEL * D_MODEL];
__device__ float g_wrv[D_MODEL * D_MODEL];
__device__ float g_wro[D_MODEL * D_MODEL];

// ---------------- helpers -----------------------------------------------------
__device__ __forceinline__ uint32_t smem_u32(const void* p) {
    return (uint32_t)__cvta_generic_to_shared(p);
}
__device__ __forceinline__ float tf32_rn(float x) {
    float r;
    asm("cvt.rna.tf32.f32 %0, %1;" : "=f"(r) : "f"(x));
    return r;
}
__device__ __forceinline__ void cp_async16(uint32_t dst, const void* src) {
    asm volatile("cp.async.cg.shared.global [%0], [%1], 16;" :: "r"(dst), "l"(src));
}
__device__ __forceinline__ void mma_tf32(float* c, const uint32_t* a, const uint32_t* b) {
    asm volatile(
        "mma.sync.aligned.m16n8k8.row.col.f32.tf32.tf32.f32 "
        "{%0,%1,%2,%3},{%4,%5,%6,%7},{%8,%9},{%0,%1,%2,%3};"
        : "+f"(c[0]), "+f"(c[1]), "+f"(c[2]), "+f"(c[3])
        : "r"(a[0]), "r"(a[1]), "r"(a[2]), "r"(a[3]), "r"(b[0]), "r"(b[1]));
}

// ---------------- prep: round fp32 -> tf32(rna) -------------------------------
__global__ void round_kernel(const float* __restrict__ X, float* __restrict__ Y)
{
    const int i = (blockIdx.x * 256 + threadIdx.x) * 4;
    float4 v = *(const float4*)(X + i);
    v.x = tf32_rn(v.x); v.y = tf32_rn(v.y); v.z = tf32_rn(v.z); v.w = tf32_rn(v.w);
    *(float4*)(Y + i) = v;
}

// ---------------- tf32 mma.sync GEMM (single-MMA, pre-rounded A) --------------
// Y[M=8192,N=1024] = A[M,K=1024] @ W[K,N] + bias
// mode 0: flat [M,N] raw; mode 1: head-split raw; mode 2: head-split tf32-rounded
#define APITCH 36    // floats, As[128][36]
#define BPITCH 136   // floats, Bs[32][136]
#define A_BUF  (128 * APITCH)
#define B_BUF  (32 * BPITCH)
#define GEMM_SMEM ((2 * A_BUF + 2 * B_BUF) * 4)   // 71680 B

__global__ __launch_bounds__(256, 2)
void mma_gemm(const float* __restrict__ A, const float* __restrict__ W,
              const float* __restrict__ bias, float* __restrict__ Y, int mode)
{
    extern __shared__ float sm[];
    float* AsF = sm;                 // [2][128][36]
    float* BsF = sm + 2 * A_BUF;     // [2][32][136]
    const uint32_t sA = smem_u32(AsF);
    const uint32_t sB = smem_u32(BsF);

    const int tid  = threadIdx.x;
    const int wid  = tid >> 5, lane = tid & 31;
    const int gid  = lane >> 2, tig = lane & 3;
    const int warp_m = wid & 1;
    const int warp_n = wid >> 1;
    const int m0 = blockIdx.y * 128;
    const int n0 = blockIdx.x * 128;

    float acc[4][4][4];
#pragma unroll
    for (int mi = 0; mi < 4; mi++)
#pragma unroll
        for (int ni = 0; ni < 4; ni++)
#pragma unroll
            for (int r = 0; r < 4; r++) acc[mi][ni][r] = 0.f;

    auto fill = [&](int kt) {
        const int buf = kt & 1;
        const uint32_t dA = sA + buf * A_BUF * 4;
        const uint32_t dB = sB + buf * B_BUF * 4;
        const float* gA = A + (size_t)m0 * D_MODEL + kt * 32;
        const float* gB = W + (size_t)kt * 32 * D_MODEL + n0;
#pragma unroll
        for (int i = 0; i < 4; i++) {
            const int f = i * 256 + tid;
            const int ra = f >> 3, ca = (f & 7) * 4;
            cp_async16(dA + (ra * APITCH + ca) * 4, gA + (size_t)ra * D_MODEL + ca);
            const int rb = f >> 5, cb = (f & 31) * 4;
            cp_async16(dB + (rb * BPITCH + cb) * 4, gB + (size_t)rb * D_MODEL + cb);
        }
        asm volatile("cp.async.commit_group;");
    };

    auto compute = [&](int kt) {
        const int buf = kt & 1;
        const float* a_s = AsF + buf * A_BUF;
        const float* b_s = BsF + buf * B_BUF;
#pragma unroll
        for (int ks = 0; ks < 4; ks++) {
            const int k0 = ks * 8;
            uint32_t af[4][4], bf[4][2];
#pragma unroll
            for (int mi = 0; mi < 4; mi++) {
                const int r = warp_m * 64 + mi * 16 + gid;
                af[mi][0] = __float_as_uint(a_s[r * APITCH + k0 + tig]);
                af[mi][1] = __float_as_uint(a_s[(r + 8) * APITCH + k0 + tig]);
                af[mi][2] = __float_as_uint(a_s[r * APITCH + k0 + tig + 4]);
                af[mi][3] = __float_as_uint(a_s[(r + 8) * APITCH + k0 + tig + 4]);
            }
#pragma unroll
            for (int ni = 0; ni < 4; ni++) {
                const int c = warp_n * 32 + ni * 8 + gid;
                bf[ni][0] = __float_as_uint(b_s[(k0 + tig) * BPITCH + c]);
                bf[ni][1] = __float_as_uint(b_s[(k0 + tig + 4) * BPITCH + c]);
            }
#pragma unroll
            for (int mi = 0; mi < 4; mi++)
#pragma unroll
                for (int ni = 0; ni < 4; ni++)
                    mma_tf32(acc[mi][ni], af[mi], bf[ni]);
        }
    };

    fill(0);
    fill(1);
    asm volatile("cp.async.wait_group 1;");
    __syncthreads();

#pragma unroll 1
    for (int kt = 0; kt < 32; kt++) {
        compute(kt);
        __syncthreads();
        if (kt + 2 < 32) {
            fill(kt + 2);
            asm volatile("cp.async.wait_group 1;");
        } else {
            asm volatile("cp.async.wait_group 0;");
        }
        __syncthreads();
    }

#pragma unroll
    for (int mi = 0; mi < 4; mi++) {
        const int r = m0 + warp_m * 64 + mi * 16 + gid;
#pragma unroll
        for (int ni = 0; ni < 4; ni++) {
            const int n = n0 + warp_n * 32 + ni * 8 + 2 * tig;
            const float bv0 = bias[n], bv1 = bias[n + 1];
            float2 lo, hi;
            lo.x = acc[mi][ni][0] + bv0; lo.y = acc[mi][ni][1] + bv1;
            hi.x = acc[mi][ni][2] + bv0; hi.y = acc[mi][ni][3] + bv1;
            if (mode == 2) {   // pre-round K/V head tensors for the attention MMAs
                lo.x = tf32_rn(lo.x); lo.y = tf32_rn(lo.y);
                hi.x = tf32_rn(hi.x); hi.y = tf32_rn(hi.y);
            }
            if (mode != 0) {
                const int h = n >> 6, d = n & 63;
                const int b0 = r >> 11, s0 = r & (SEQ - 1);
                const int b1 = (r + 8) >> 11, s1 = (r + 8) & (SEQ - 1);
                *(float2*)&Y[(size_t)(((b0 * NHEAD + h) * SEQ) + s0) * DEPTH + d] = lo;
                *(float2*)&Y[(size_t)(((b1 * NHEAD + h) * SEQ) + s1) * DEPTH + d] = hi;
            } else {
                *(float2*)&Y[(size_t)r * D_MODEL + n] = lo;
                *(float2*)&Y[(size_t)(r + 8) * D_MODEL + n] = hi;
            }
        }
    }
}

// ---------------- tensor-core flash attention ---------------------------------
// grid (SEQ/128, NHEAD, BATCH), 256 threads (8 warps), warp w owns rows 16w..16w+15
// K/V arrive tf32-rounded from the projections; Q raw fp32 (2-term split here).
#define ABR 128
#define ABC 32
#define QP  68
#define KP  68
#define VP  72
#define ATTN_SMEM ((ABR*QP + 2*ABC*KP + 2*ABC*VP) * 4)   // 70656 B

__global__ __launch_bounds__(256, 2)
void attn_tc(const float* __restrict__ Qh, const float* __restrict__ Kh,
             const float* __restrict__ Vh, float* __restrict__ O)
{
    extern __shared__ float smf[];
    float* q_s = smf;                         // [128][68]
    float* k_s = smf + ABR * QP;              // [2][32][68]
    float* v_s = k_s + 2 * ABC * KP;          // [2][32][72]
    const uint32_t sK = smem_u32(k_s);
    const uint32_t sV = smem_u32(v_s);

    const int qt = blockIdx.x;
    const int h  = blockIdx.y;
    const int b  = blockIdx.z;
    const int tid = threadIdx.x;
    const int w = tid >> 5, lane = tid & 31;
    const int gid = lane >> 2, tig = lane & 3;

    const float* Qb = Qh + (size_t)(((b * NHEAD + h) * SEQ) + qt * ABR) * DEPTH;
    const float* Kb = Kh + (size_t)((b * NHEAD + h) * SEQ) * DEPTH;
    const float* Vb = Vh + (size_t)((b * NHEAD + h) * SEQ) * DEPTH;

    // load Q (scaled by 1/sqrt(depth)) into smem
#pragma unroll
    for (int i = 0; i < 8; i++) {
        const int f4 = i * 256 + tid;
        const int r = f4 >> 4, c = (f4 & 15) * 4;
        float4 qv = *(const float4*)(Qb + (size_t)r * DEPTH + c);
        qv.x *= 0.125f; qv.y *= 0.125f; qv.z *= 0.125f; qv.w *= 0.125f;
        *(float4*)&q_s[r * QP + c] = qv;
    }

    auto fill = [&](int kt) {
        const int buf = kt & 1;
        const float* gK = Kb + (size_t)kt * ABC * DEPTH;
        const float* gV = Vb + (size_t)kt * ABC * DEPTH;
#pragma unroll
        for (int i = 0; i < 2; i++) {
            const int f4 = i * 256 + tid;
            const int r = f4 >> 4, c = (f4 & 15) * 4;
            cp_async16(sK + (buf * ABC * KP + r * KP + c) * 4, gK + (size_t)r * DEPTH + c);
            cp_async16(sV + (buf * ABC * VP + r * VP + c) * 4, gV + (size_t)r * DEPTH + c);
        }
        asm volatile("cp.async.commit_group;");
    };

    float m0 = -1e30f, m1 = -1e30f, l0 = 0.f, l1 = 0.f;
    float o[8][4];
#pragma unroll
    for (int nt = 0; nt < 8; nt++)
#pragma unroll
        for (int r = 0; r < 4; r++) o[nt][r] = 0.f;

    fill(0);
    __syncthreads();   // also covers q_s stores vs first frag reads

#pragma unroll 1
    for (int kt = 0; kt < SEQ / ABC; kt++) {
        if (kt + 1 < SEQ / ABC) {
            fill(kt + 1);
            asm volatile("cp.async.wait_group 1;");
        } else {
            asm volatile("cp.async.wait_group 0;");
        }
        __syncthreads();

        const float* ks_ = k_s + (kt & 1) * ABC * KP;
        const float* vs_ = v_s + (kt & 1) * ABC * VP;

        // ---- S = Q K^T (Q 2-term split; K already tf32) ----
        float s[4][4];
#pragma unroll
        for (int nt = 0; nt < 4; nt++)
#pragma unroll
            for (int r = 0; r < 4; r++) s[nt][r] = 0.f;

#pragma unroll
        for (int ks = 0; ks < 8; ks++) {
            const int k0 = ks * 8;
            const int qr = 16 * w + gid;
            float f0 = q_s[qr * QP + k0 + tig];
            float f1 = q_s[(qr + 8) * QP + k0 + tig];
            float f2 = q_s[qr * QP + k0 + tig + 4];
            float f3 = q_s[(qr + 8) * QP + k0 + tig + 4];
            float h0 = tf32_rn(f0), h1 = tf32_rn(f1), h2 = tf32_rn(f2), h3 = tf32_rn(f3);
            uint32_t ah[4] = {__float_as_uint(h0), __float_as_uint(h1),
                              __float_as_uint(h2), __float_as_uint(h3)};
            uint32_t al[4] = {__float_as_uint(tf32_rn(f0 - h0)), __float_as_uint(tf32_rn(f1 - h1)),
                              __float_as_uint(tf32_rn(f2 - h2)), __float_as_uint(tf32_rn(f3 - h3))};
#pragma unroll
            for (int nt = 0; nt < 4; nt++) {
                uint32_t bh[2];
                bh[0] = __float_as_uint(ks_[(8 * nt + gid) * KP + k0 + tig]);
                bh[1] = __float_as_uint(ks_[(8 * nt + gid) * KP + k0 + tig + 4]);
                mma_tf32(s[nt], ah, bh);
                mma_tf32(s[nt], al, bh);
            }
        }

        // ---- online softmax ----
        float smax0 = -1e30f, smax1 = -1e30f;
#pragma unroll
        for (int nt = 0; nt < 4; nt++) {
            smax0 = fmaxf(smax0, fmaxf(s[nt][0], s[nt][1]));
            smax1 = fmaxf(smax1, fmaxf(s[nt][2], s[nt][3]));
        }
#pragma unroll
        for (int off = 1; off <= 2; off <<= 1) {
            smax0 = fmaxf(smax0, __shfl_xor_sync(0xffffffffu, smax0, off));
            smax1 = fmaxf(smax1, __shfl_xor_sync(0xffffffffu, smax1, off));
        }
        const float mn0 = fmaxf(m0, smax0), mn1 = fmaxf(m1, smax1);
        const float cr0 = __expf(m0 - mn0), cr1 = __expf(m1 - mn1);
        float sum0 = 0.f, sum1 = 0.f;
#pragma unroll
        for (int nt = 0; nt < 4; nt++) {
            s[nt][0] = __expf(s[nt][0] - mn0);
            s[nt][1] = __expf(s[nt][1] - mn0);
            s[nt][2] = __expf(s[nt][2] - mn1);
            s[nt][3] = __expf(s[nt][3] - mn1);
            sum0 += s[nt][0] + s[nt][1];
            sum1 += s[nt][2] + s[nt][3];
        }
#pragma unroll
        for (int off = 1; off <= 2; off <<= 1) {
            sum0 += __shfl_xor_sync(0xffffffffu, sum0, off);
            sum1 += __shfl_xor_sync(0xffffffffu, sum1, off);
        }
        l0 = l0 * cr0 + sum0; l1 = l1 * cr1 + sum1;
        m0 = mn0; m1 = mn1;
#pragma unroll
        for (int nt = 0; nt < 8; nt++) {
            o[nt][0] *= cr0; o[nt][1] *= cr0;
            o[nt][2] *= cr1; o[nt][3] *= cr1;
        }

        // ---- O += P V (P A-fragments via quad shuffles; V already tf32) ----
        const int src1 = (lane & ~3) | (tig >> 1);
        const int src2 = src1 + 2;
        const bool odd = tig & 1;
#pragma unroll
        for (int kc = 0; kc < 4; kc++) {
            float x0 = __shfl_sync(0xffffffffu, s[kc][0], src1);
            float x1 = __shfl_sync(0xffffffffu, s[kc][1], src1);
            float x2 = __shfl_sync(0xffffffffu, s[kc][2], src1);
            float x3 = __shfl_sync(0xffffffffu, s[kc][3], src1);
            float y0 = __shfl_sync(0xffffffffu, s[kc][0], src2);
            float y1 = __shfl_sync(0xffffffffu, s[kc][1], src2);
            float y2 = __shfl_sync(0xffffffffu, s[kc][2], src2);
            float y3 = __shfl_sync(0xffffffffu, s[kc][3], src2);
            uint32_t ap[4];
            ap[0] = __float_as_uint(tf32_rn(odd ? x1 : x0));   // P[gid   ][8kc+tig  ]
            ap[1] = __float_as_uint(tf32_rn(odd ? x3 : x2));   // P[gid+8 ][8kc+tig  ]
            ap[2] = __float_as_uint(tf32_rn(odd ? y1 : y0));   // P[gid   ][8kc+tig+4]
            ap[3] = __float_as_uint(tf32_rn(odd ? y3 : y2));   // P[gid+8 ][8kc+tig+4]
#pragma unroll
            for (int nt = 0; nt < 8; nt++) {
                uint32_t bv[2];
                bv[0] = __float_as_uint(vs_[(8 * kc + tig) * VP + 8 * nt + gid]);
                bv[1] = __float_as_uint(vs_[(8 * kc + tig + 4) * VP + 8 * nt + gid]);
                mma_tf32(o[nt], ap, bv);
            }
        }
        __syncthreads();   // done reading this buffer before it is refilled
    }

    // epilogue: normalize, round to tf32, write [B,S,D] flat (feeds out-proj A)
    const float inv0 = 1.f / l0, inv1 = 1.f / l1;
    const int r0 = qt * ABR + 16 * w + gid;
    const int r1 = r0 + 8;
#pragma unroll
    for (int nt = 0; nt < 8; nt++) {
        const int d = h * DEPTH + 8 * nt + 2 * tig;
        float2 lo, hi;
        lo.x = tf32_rn(o[nt][0] * inv0); lo.y = tf32_rn(o[nt][1] * inv0);
        hi.x = tf32_rn(o[nt][2] * inv1); hi.y = tf32_rn(o[nt][3] * inv1);
        *(float2*)&O[(size_t)(b * SEQ + r0) * D_MODEL + d] = lo;
        *(float2*)&O[(size_t)(b * SEQ + r1) * D_MODEL + d] = hi;
    }
}

// ---------------- launch -------------------------------------------------------
extern "C" void kernel_launch(void* const* d_in, const int* in_sizes, int n_in,
                              void* d_out, int out_size)
{
    const float* v  = (const float*)d_in[0];
    const float* k  = (const float*)d_in[1];
    const float* q  = (const float*)d_in[2];
    const float* wq = (const float*)d_in[3];
    const float* bq = (const float*)d_in[4];
    const float* wk = (const float*)d_in[5];
    const float* bk = (const float*)d_in[6];
    const float* wv = (const float*)d_in[7];
    const float* bv = (const float*)d_in[8];
    const float* wo = (const float*)d_in[9];
    const float* bo = (const float*)d_in[10];
    float* out = (float*)d_out;

    float *p_qh, *p_kh, *p_vh, *p_attn, *p_qr, *p_kr, *p_vr;
    float *p_wrq, *p_wrk, *p_wrv, *p_wro;
    cudaGetSymbolAddress((void**)&p_qh,   g_qh);
    cudaGetSymbolAddress((void**)&p_kh,   g_kh);
    cudaGetSymbolAddress((void**)&p_vh,   g_vh);
    cudaGetSymbolAddress((void**)&p_attn, g_attn);
    cudaGetSymbolAddress((void**)&p_qr,   g_qr);
    cudaGetSymbolAddress((void**)&p_kr,   g_kr);
    cudaGetSymbolAddress((void**)&p_vr,   g_vr);
    cudaGetSymbolAddress((void**)&p_wrq,  g_wrq);
    cudaGetSymbolAddress((void**)&p_wrk,  g_wrk);
    cudaGetSymbolAddress((void**)&p_wrv,  g_wrv);
    cudaGetSymbolAddress((void**)&p_wro,  g_wro);

    cudaFuncSetAttribute(mma_gemm, cudaFuncAttributeMaxDynamicSharedMemorySize, GEMM_SMEM);
    cudaFuncSetAttribute(attn_tc,  cudaFuncAttributeMaxDynamicSharedMemorySize, ATTN_SMEM);

    // prep: round activations + weights to tf32-representable values
    const int rblocks_act = (MROWS * D_MODEL) / (256 * 4);
    const int rblocks_w   = (D_MODEL * D_MODEL) / (256 * 4);
    round_kernel<<<rblocks_act, 256>>>(q, p_qr);
    round_kernel<<<rblocks_act, 256>>>(k, p_kr);
    round_kernel<<<rblocks_act, 256>>>(v, p_vr);
    round_kernel<<<rblocks_w, 256>>>(wq, p_wrq);
    round_kernel<<<rblocks_w, 256>>>(wk, p_wrk);
    round_kernel<<<rblocks_w, 256>>>(wv, p_wrv);
    round_kernel<<<rblocks_w, 256>>>(wo, p_wro);

    // projections (tf32 tensor, single-MMA)
    dim3 ggrid(D_MODEL / 128, MROWS / 128);   // (8, 64)
    mma_gemm<<<ggrid, 256, GEMM_SMEM>>>(p_qr, p_wrq, bq, p_qh, 1);  // Q: raw out
    mma_gemm<<<ggrid, 256, GEMM_SMEM>>>(p_kr, p_wrk, bk, p_kh, 2);  // K: tf32 out
    mma_gemm<<<ggrid, 256, GEMM_SMEM>>>(p_vr, p_wrv, bv, p_vh, 2);  // V: tf32 out

    // attention (tf32 tensor, flash)
    dim3 agrid(SEQ / ABR, NHEAD, BATCH);      // (16, 16, 4)
    attn_tc<<<agrid, 256, ATTN_SMEM>>>(p_qh, p_kh, p_vh, p_attn);

    // output projection
    mma_gemm<<<ggrid, 256, GEMM_SMEM>>>(p_attn, p_wro, bo, out, 0);
}

// round 8
// speedup vs baseline: 5.8803x; 1.7641x over previous
#include <cuda_runtime.h>
#include <cuda_fp16.h>
#include <cstdint>

#define D_MODEL 1024
#define NHEAD   16
#define DEPTH   64
#define SEQ     2048
#define BATCH   4
#define MROWS   (BATCH*SEQ)   // 8192

// ---------------- scratch (device globals; no allocs allowed) ----------------
__device__ __half g_q16[MROWS * D_MODEL];    // fp16 inputs (A operands)
__device__ __half g_k16[MROWS * D_MODEL];
__device__ __half g_v16[MROWS * D_MODEL];
__device__ __half g_w16q[D_MODEL * D_MODEL]; // W, k-pair-interleaved half2 [K/2][N]
__device__ __half g_w16k[D_MODEL * D_MODEL];
__device__ __half g_w16v[D_MODEL * D_MODEL];
__device__ __half g_w16o[D_MODEL * D_MODEL];
__device__ float  g_qh  [MROWS * D_MODEL];   // Q proj out, fp32 head-split [BH][S][D]
__device__ __half g_kh16[MROWS * D_MODEL];   // K proj out, fp16 head-split [BH][S][D]
__device__ __half g_vh16[MROWS * D_MODEL];   // V proj out, fp16 key-pair-interleaved [BH][S/2][D][2]
__device__ __half g_attn16[MROWS * D_MODEL]; // attn out, fp16 flat [B*S][D_MODEL]

// ---------------- helpers -----------------------------------------------------
__device__ __forceinline__ uint32_t smem_u32(const void* p) {
    return (uint32_t)__cvta_generic_to_shared(p);
}
__device__ __forceinline__ void cp_async16(uint32_t dst, const void* src) {
    asm volatile("cp.async.cg.shared.global [%0], [%1], 16;" :: "r"(dst), "l"(src));
}
__device__ __forceinline__ uint32_t pack_h2(float x, float y) {
    __half2 h = __floats2half2_rn(x, y);
    return *(uint32_t*)&h;
}
__device__ __forceinline__ void mma_f16(float* c, const uint32_t* a, const uint32_t* b) {
    asm volatile(
        "mma.sync.aligned.m16n8k16.row.col.f32.f16.f16.f32 "
        "{%0,%1,%2,%3},{%4,%5,%6,%7},{%8,%9},{%0,%1,%2,%3};"
        : "+f"(c[0]), "+f"(c[1]), "+f"(c[2]), "+f"(c[3])
        : "r"(a[0]), "r"(a[1]), "r"(a[2]), "r"(a[3]), "r"(b[0]), "r"(b[1]));
}

// ---------------- prep kernels -------------------------------------------------
__global__ void cvt_half(const float* __restrict__ X, __half* __restrict__ Y)
{
    const int i = (blockIdx.x * 256 + threadIdx.x) * 4;
    float4 v = *(const float4*)(X + i);
    __half2* Y2 = (__half2*)(Y + i);
    Y2[0] = __floats2half2_rn(v.x, v.y);
    Y2[1] = __floats2half2_rn(v.z, v.w);
}
// W [K][N] fp32 -> k-pair-interleaved half2: WH2[kp][n] = (W[2kp][n], W[2kp+1][n])
__global__ void wprep(const float* __restrict__ W, __half* __restrict__ WH)
{
    const int idx = blockIdx.x * 256 + threadIdx.x;
    const int kp = idx >> 8;
    const int n  = (idx & 255) * 4;
    float4 a = *(const float4*)(W + (size_t)(2 * kp) * D_MODEL + n);
    float4 b = *(const float4*)(W + (size_t)(2 * kp + 1) * D_MODEL + n);
    __half2* out = (__half2*)WH + (size_t)kp * D_MODEL + n;
    out[0] = __halves2half2(__float2half_rn(a.x), __float2half_rn(b.x));
    out[1] = __halves2half2(__float2half_rn(a.y), __float2half_rn(b.y));
    out[2] = __halves2half2(__float2half_rn(a.z), __float2half_rn(b.z));
    out[3] = __halves2half2(__float2half_rn(a.w), __float2half_rn(b.w));
}

// ---------------- fp16 mma.sync GEMM -------------------------------------------
// Y = A[M,1024] @ W[1024,1024] + bias.  A fp16 natural; W fp16 interleaved half2.
// mode 0: flat fp32; 1: head-split fp32; 2: head-split fp16; 3: head-split fp16 V-interleaved
#define AP2 20            // A pitch in half2 (40 halves = 80B)
#define BP2 136           // B pitch in half2 (544B)
#define A_STG_B 10240     // 128 * 80
#define B_STG_B 8704      // 16 * 544
#define A_STG_U 2560      // half2 units
#define B_STG_U 2176
#define GEMM_SMEM (2 * (A_STG_B + B_STG_B))   // 37888 B

__global__ __launch_bounds__(256, 2)
void mma_gemm(const __half* __restrict__ A, const __half* __restrict__ WH,
              const float* __restrict__ bias, void* __restrict__ Yv, int mode)
{
    extern __shared__ char smc[];
    uint32_t* AsU = (uint32_t*)smc;                       // [2][128][20] half2
    uint32_t* BsU = (uint32_t*)(smc + 2 * A_STG_B);       // [2][16][136] half2
    const uint32_t sA = smem_u32(AsU);
    const uint32_t sB = smem_u32(BsU);

    const int tid  = threadIdx.x;
    const int wid  = tid >> 5, lane = tid & 31;
    const int gid  = lane >> 2, tig = lane & 3;
    const int warp_m = wid & 1;
    const int warp_n = wid >> 1;
    const int m0 = blockIdx.y * 128;
    const int n0 = blockIdx.x * 128;

    float acc[4][4][4];
#pragma unroll
    for (int mi = 0; mi < 4; mi++)
#pragma unroll
        for (int ni = 0; ni < 4; ni++)
#pragma unroll
            for (int r = 0; r < 4; r++) acc[mi][ni][r] = 0.f;

    auto fill = [&](int kt) {
        const int buf = kt & 1;
        const uint32_t dA = sA + buf * A_STG_B;
        const uint32_t dB = sB + buf * B_STG_B;
        const __half* gA = A + (size_t)m0 * D_MODEL + kt * 32;
        const uint32_t* gB = (const uint32_t*)WH + (size_t)(kt * 16) * D_MODEL + n0;
#pragma unroll
        for (int i = 0; i < 2; i++) {
            const int f = i * 256 + tid;
            const int ra = f >> 2, ca = (f & 3) * 8;            // A: 128 rows x 4 chunks
            cp_async16(dA + ra * 80 + ca * 2, gA + (size_t)ra * D_MODEL + ca);
            const int rb = f >> 5, cb = (f & 31) * 4;           // B: 16 rows x 32 chunks
            cp_async16(dB + rb * 544 + cb * 4, gB + (size_t)rb * D_MODEL + cb);
        }
        asm volatile("cp.async.commit_group;");
    };

    auto compute = [&](int kt) {
        const int buf = kt & 1;
        const uint32_t* a_s = AsU + buf * A_STG_U;
        const uint32_t* b_s = BsU + buf * B_STG_U;
#pragma unroll
        for (int ks = 0; ks < 2; ks++) {
            const int k8 = ks * 8;
            uint32_t af[4][4], bf[4][2];
#pragma unroll
            for (int mi = 0; mi < 4; mi++) {
                const int r = warp_m * 64 + mi * 16 + gid;
                af[mi][0] = a_s[r * AP2 + k8 + tig];
                af[mi][1] = a_s[(r + 8) * AP2 + k8 + tig];
                af[mi][2] = a_s[r * AP2 + k8 + tig + 4];
                af[mi][3] = a_s[(r + 8) * AP2 + k8 + tig + 4];
            }
#pragma unroll
            for (int ni = 0; ni < 4; ni++) {
                const int c = warp_n * 32 + ni * 8 + gid;
                bf[ni][0] = b_s[(k8 + tig) * BP2 + c];
                bf[ni][1] = b_s[(k8 + tig + 4) * BP2 + c];
            }
#pragma unroll
            for (int mi = 0; mi < 4; mi++)
#pragma unroll
                for (int ni = 0; ni < 4; ni++)
                    mma_f16(acc[mi][ni], af[mi], bf[ni]);
        }
    };

    fill(0);
    fill(1);
    asm volatile("cp.async.wait_group 1;");
    __syncthreads();

#pragma unroll 1
    for (int kt = 0; kt < 32; kt++) {
        compute(kt);
        __syncthreads();
        if (kt + 2 < 32) {
            fill(kt + 2);
            asm volatile("cp.async.wait_group 1;");
        } else {
            asm volatile("cp.async.wait_group 0;");
        }
        __syncthreads();
    }

#pragma unroll
    for (int mi = 0; mi < 4; mi++) {
        const int r = m0 + warp_m * 64 + mi * 16 + gid;
#pragma unroll
        for (int ni = 0; ni < 4; ni++) {
            const int n = n0 + warp_n * 32 + ni * 8 + 2 * tig;
            const float bv0 = bias[n], bv1 = bias[n + 1];
            float2 lo, hi;
            lo.x = acc[mi][ni][0] + bv0; lo.y = acc[mi][ni][1] + bv1;
            hi.x = acc[mi][ni][2] + bv0; hi.y = acc[mi][ni][3] + bv1;
            if (mode == 0) {
                float* Y = (float*)Yv;
                *(float2*)&Y[(size_t)r * D_MODEL + n] = lo;
                *(float2*)&Y[(size_t)(r + 8) * D_MODEL + n] = hi;
            } else {
                const int h = n >> 6, d = n & 63;
                const int b0 = r >> 11, s0 = r & (SEQ - 1);
                const int bh = b0 * NHEAD + h;
                const int s1 = ((r + 8) & (SEQ - 1));
                if (mode == 1) {
                    float* Y = (float*)Yv;
                    *(float2*)&Y[(size_t)(bh * SEQ + s0) * DEPTH + d] = lo;
                    *(float2*)&Y[(size_t)(bh * SEQ + s1) * DEPTH + d] = hi;
                } else if (mode == 2) {
                    __half2* Y = (__half2*)Yv;
                    Y[(size_t)(bh * SEQ + s0) * (DEPTH / 2) + (d >> 1)] = __floats2half2_rn(lo.x, lo.y);
                    Y[(size_t)(bh * SEQ + s1) * (DEPTH / 2) + (d >> 1)] = __floats2half2_rn(hi.x, hi.y);
                } else {   // mode 3: V key-pair interleaved
                    __half* Y = (__half*)Yv;
                    size_t i0 = (((size_t)bh * (SEQ / 2) + (s0 >> 1)) * DEPTH + d) * 2 + (s0 & 1);
                    size_t i1 = (((size_t)bh * (SEQ / 2) + (s1 >> 1)) * DEPTH + d) * 2 + (s1 & 1);
                    Y[i0]     = __float2half_rn(lo.x);
                    Y[i0 + 2] = __float2half_rn(lo.y);
                    Y[i1]     = __float2half_rn(hi.x);
                    Y[i1 + 2] = __float2half_rn(hi.y);
                }
            }
        }
    }
}

// ---------------- fp16 tensor-core flash attention -----------------------------
// grid (SEQ/128, NHEAD, BATCH), 256 thr. Q: fp32 in, hi/lo fp16 split in smem.
#define ABR 128
#define ABC 32
#define QP2 36   // q pitch, half2 (72 halves, 144B)
#define KP2 36   // k pitch, half2: 32 used + 4 pad (row = 64 halves = 128B)
#define VP2 72   // v pitch, half2 (64 used + 8 pad; pair-row = 128 halves = 256B)
#define Q_STG_U (128 * QP2)        // 4608 half2 per (hi|lo)
#define K_STG_U (32 * KP2)         // 1152
#define V_STG_U (16 * VP2)         // 1152
#define K_STG_B (K_STG_U * 4)
#define V_STG_B (V_STG_U * 4)
#define ATTN_SMEM ((2 * Q_STG_U + 2 * K_STG_U + 2 * V_STG_U) * 4)   // 55296 B

__global__ __launch_bounds__(256, 2)
void attn_tc(const float* __restrict__ Qh, const __half* __restrict__ Kh,
             const __half* __restrict__ Vh, __half* __restrict__ O)
{
    extern __shared__ char smc[];
    uint32_t* qhi = (uint32_t*)smc;                    // [128][36]
    uint32_t* qlo = qhi + Q_STG_U;
    uint32_t* ksm = qlo + Q_STG_U;                     // [2][32][36]
    uint32_t* vsm = ksm + 2 * K_STG_U;                 // [2][16][72]
    const uint32_t sK = smem_u32(ksm);
    const uint32_t sV = smem_u32(vsm);

    const int qt = blockIdx.x;
    const int h  = blockIdx.y;
    const int b  = blockIdx.z;
    const int tid = threadIdx.x;
    const int w = tid >> 5, lane = tid & 31;
    const int gid = lane >> 2, tig = lane & 3;
    const int bh = b * NHEAD + h;

    const float*    Qb  = Qh + (size_t)(bh * SEQ + qt * ABR) * DEPTH;
    const __half*   Kb  = Kh + (size_t)(bh * SEQ) * DEPTH;
    const uint32_t* Vb2 = (const uint32_t*)Vh + (size_t)bh * (SEQ / 2) * DEPTH;

    // load Q, scale, split hi/lo fp16
#pragma unroll
    for (int i = 0; i < 8; i++) {
        const int f4 = i * 256 + tid;
        const int r = f4 >> 4, c = (f4 & 15) * 4;
        float4 qv = *(const float4*)(Qb + (size_t)r * DEPTH + c);
        qv.x *= 0.125f; qv.y *= 0.125f; qv.z *= 0.125f; qv.w *= 0.125f;
        __half hx = __float2half_rn(qv.x), hy = __float2half_rn(qv.y);
        __half hz = __float2half_rn(qv.z), hw = __float2half_rn(qv.w);
        __half2 h01 = __halves2half2(hx, hy), h23 = __halves2half2(hz, hw);
        qhi[r * QP2 + (c >> 1)]     = *(uint32_t*)&h01;
        qhi[r * QP2 + (c >> 1) + 1] = *(uint32_t*)&h23;
        qlo[r * QP2 + (c >> 1)]     = pack_h2(qv.x - __half2float(hx), qv.y - __half2float(hy));
        qlo[r * QP2 + (c >> 1) + 1] = pack_h2(qv.z - __half2float(hz), qv.w - __half2float(hw));
    }

    auto fill = [&](int kt) {
        const int buf = kt & 1;
        {   // K tile: 32 rows x 128B -> 256 cp.async (row = tid>>3, 8 chunks/row)
            const int r = tid >> 3, c = (tid & 7) * 8;   // c in halves
            const __half* gK = Kb + (size_t)(kt * ABC) * DEPTH;
            cp_async16(sK + buf * K_STG_B + r * (KP2 * 4) + c * 2, gK + (size_t)r * DEPTH + c);
        }
        {   // V tile: 16 pair-rows x 256B -> 256 cp.async
            const int rp = tid >> 4, c4 = (tid & 15) * 4;   // c4 in half2 units
            const uint32_t* gV = Vb2 + (size_t)(kt * 16) * DEPTH;
            cp_async16(sV + buf * V_STG_B + rp * (VP2 * 4) + c4 * 4, gV + (size_t)rp * DEPTH + c4);
        }
        asm volatile("cp.async.commit_group;");
    };

    float m0 = -1e30f, m1 = -1e30f, l0 = 0.f, l1 = 0.f;
    float o[8][4];
#pragma unroll
    for (int nt = 0; nt < 8; nt++)
#pragma unroll
        for (int r = 0; r < 4; r++) o[nt][r] = 0.f;

    fill(0);
    __syncthreads();   // covers q smem stores too

#pragma unroll 1
    for (int kt = 0; kt < SEQ / ABC; kt++) {
        if (kt + 1 < SEQ / ABC) {
            fill(kt + 1);
            asm volatile("cp.async.wait_group 1;");
        } else {
            asm volatile("cp.async.wait_group 0;");
        }
        __syncthreads();

        const uint32_t* ks_ = ksm + (kt & 1) * K_STG_U;
        const uint32_t* vs_ = vsm + (kt & 1) * V_STG_U;

        // ---- S = Q K^T (Q hi+lo fp16 split; K fp16) ----
        float s[4][4];
#pragma unroll
        for (int nt = 0; nt < 4; nt++)
#pragma unroll
            for (int r = 0; r < 4; r++) s[nt][r] = 0.f;

        const int qr = 16 * w + gid;
#pragma unroll
        for (int ks = 0; ks < 4; ks++) {
            const int k8 = ks * 8;
            uint32_t ah[4], al[4];
            ah[0] = qhi[qr * QP2 + k8 + tig];
            ah[1] = qhi[(qr + 8) * QP2 + k8 + tig];
            ah[2] = qhi[qr * QP2 + k8 + tig + 4];
            ah[3] = qhi[(qr + 8) * QP2 + k8 + tig + 4];
            al[0] = qlo[qr * QP2 + k8 + tig];
            al[1] = qlo[(qr + 8) * QP2 + k8 + tig];
            al[2] = qlo[qr * QP2 + k8 + tig + 4];
            al[3] = qlo[(qr + 8) * QP2 + k8 + tig + 4];
#pragma unroll
            for (int nt = 0; nt < 4; nt++) {
                uint32_t bh2[2];
                const int key = 8 * nt + gid;
                bh2[0] = ks_[key * KP2 + k8 + tig];
                bh2[1] = ks_[key * KP2 + k8 + tig + 4];
                mma_f16(s[nt], ah, bh2);
                mma_f16(s[nt], al, bh2);
            }
        }

        // ---- online softmax ----
        float smax0 = -1e30f, smax1 = -1e30f;
#pragma unroll
        for (int nt = 0; nt < 4; nt++) {
            smax0 = fmaxf(smax0, fmaxf(s[nt][0], s[nt][1]));
            smax1 = fmaxf(smax1, fmaxf(s[nt][2], s[nt][3]));
        }
#pragma unroll
        for (int off = 1; off <= 2; off <<= 1) {
            smax0 = fmaxf(smax0, __shfl_xor_sync(0xffffffffu, smax0, off));
            smax1 = fmaxf(smax1, __shfl_xor_sync(0xffffffffu, smax1, off));
        }
        const float mn0 = fmaxf(m0, smax0), mn1 = fmaxf(m1, smax1);
        const float cr0 = __expf(m0 - mn0), cr1 = __expf(m1 - mn1);
        float sum0 = 0.f, sum1 = 0.f;
#pragma unroll
        for (int nt = 0; nt < 4; nt++) {
            s[nt][0] = __expf(s[nt][0] - mn0);
            s[nt][1] = __expf(s[nt][1] - mn0);
            s[nt][2] = __expf(s[nt][2] - mn1);
            s[nt][3] = __expf(s[nt][3] - mn1);
            sum0 += s[nt][0] + s[nt][1];
            sum1 += s[nt][2] + s[nt][3];
        }
#pragma unroll
        for (int off = 1; off <= 2; off <<= 1) {
            sum0 += __shfl_xor_sync(0xffffffffu, sum0, off);
            sum1 += __shfl_xor_sync(0xffffffffu, sum1, off);
        }
        l0 = l0 * cr0 + sum0; l1 = l1 * cr1 + sum1;
        m0 = mn0; m1 = mn1;
#pragma unroll
        for (int nt = 0; nt < 8; nt++) {
            o[nt][0] *= cr0; o[nt][1] *= cr0;
            o[nt][2] *= cr1; o[nt][3] *= cr1;
        }

        // ---- O += P V : QK C-fragments ARE PV A-fragments (fp16 k16) ----
#pragma unroll
        for (int kc = 0; kc < 2; kc++) {
            uint32_t ap[4];
            ap[0] = pack_h2(s[2 * kc][0],     s[2 * kc][1]);
            ap[1] = pack_h2(s[2 * kc][2],     s[2 * kc][3]);
            ap[2] = pack_h2(s[2 * kc + 1][0], s[2 * kc + 1][1]);
            ap[3] = pack_h2(s[2 * kc + 1][2], s[2 * kc + 1][3]);
#pragma unroll
            for (int nt = 0; nt < 8; nt++) {
                uint32_t bv[2];
                const int d = 8 * nt + gid;
                bv[0] = vs_[(kc * 8 + tig) * VP2 + d];
                bv[1] = vs_[(kc * 8 + tig + 4) * VP2 + d];
                mma_f16(o[nt], ap, bv);
            }
        }
        __syncthreads();
    }

    // epilogue: normalize, fp16, write flat [B*S][D_MODEL]
    const float inv0 = 1.f / l0, inv1 = 1.f / l1;
    const int r0 = qt * ABR + 16 * w + gid;
    const int r1 = r0 + 8;
    uint32_t* O2 = (uint32_t*)O;
#pragma unroll
    for (int nt = 0; nt < 8; nt++) {
        const int d = h * DEPTH + 8 * nt + 2 * tig;
        O2[((size_t)(b * SEQ + r0) * D_MODEL + d) >> 1] = pack_h2(o[nt][0] * inv0, o[nt][1] * inv0);
        O2[((size_t)(b * SEQ + r1) * D_MODEL + d) >> 1] = pack_h2(o[nt][2] * inv1, o[nt][3] * inv1);
    }
}

// ---------------- launch -------------------------------------------------------
extern "C" void kernel_launch(void* const* d_in, const int* in_sizes, int n_in,
                              void* d_out, int out_size)
{
    const float* v  = (const float*)d_in[0];
    const float* k  = (const float*)d_in[1];
    const float* q  = (const float*)d_in[2];
    const float* wq = (const float*)d_in[3];
    const float* bq = (const float*)d_in[4];
    const float* wk = (const float*)d_in[5];
    const float* bk = (const float*)d_in[6];
    const float* wv = (const float*)d_in[7];
    const float* bv = (const float*)d_in[8];
    const float* wo = (const float*)d_in[9];
    const float* bo = (const float*)d_in[10];
    float* out = (float*)d_out;

    __half *p_q16, *p_k16, *p_v16, *p_w16q, *p_w16k, *p_w16v, *p_w16o;
    __half *p_kh16, *p_vh16, *p_attn16;
    float  *p_qh;
    cudaGetSymbolAddress((void**)&p_q16,   g_q16);
    cudaGetSymbolAddress((void**)&p_k16,   g_k16);
    cudaGetSymbolAddress((void**)&p_v16,   g_v16);
    cudaGetSymbolAddress((void**)&p_w16q,  g_w16q);
    cudaGetSymbolAddress((void**)&p_w16k,  g_w16k);
    cudaGetSymbolAddress((void**)&p_w16v,  g_w16v);
    cudaGetSymbolAddress((void**)&p_w16o,  g_w16o);
    cudaGetSymbolAddress((void**)&p_qh,    g_qh);
    cudaGetSymbolAddress((void**)&p_kh16,  g_kh16);
    cudaGetSymbolAddress((void**)&p_vh16,  g_vh16);
    cudaGetSymbolAddress((void**)&p_attn16, g_attn16);

    cudaFuncSetAttribute(mma_gemm, cudaFuncAttributeMaxDynamicSharedMemorySize, GEMM_SMEM);
    cudaFuncSetAttribute(attn_tc,  cudaFuncAttributeMaxDynamicSharedMemorySize, ATTN_SMEM);

    // prep: convert activations + weights to fp16
    const int cblocks_act = (MROWS * D_MODEL) / (256 * 4);
    const int wgrid = (D_MODEL / 2) * (D_MODEL / 4) / 256;
    cvt_half<<<cblocks_act, 256>>>(q, p_q16);
    cvt_half<<<cblocks_act, 256>>>(k, p_k16);
    cvt_half<<<cblocks_act, 256>>>(v, p_v16);
    wprep<<<wgrid, 256>>>(wq, p_w16q);
    wprep<<<wgrid, 256>>>(wk, p_w16k);
    wprep<<<wgrid, 256>>>(wv, p_w16v);
    wprep<<<wgrid, 256>>>(wo, p_w16o);

    // projections (fp16 tensor)
    dim3 ggrid(D_MODEL / 128, MROWS / 128);   // (8, 64)
    mma_gemm<<<ggrid, 256, GEMM_SMEM>>>(p_q16, p_w16q, bq, p_qh,   1);  // Q: fp32 head-split
    mma_gemm<<<ggrid, 256, GEMM_SMEM>>>(p_k16, p_w16k, bk, p_kh16, 2);  // K: fp16 head-split
    mma_gemm<<<ggrid, 256, GEMM_SMEM>>>(p_v16, p_w16v, bv, p_vh16, 3);  // V: fp16 interleaved

    // attention (fp16 tensor, flash)
    dim3 agrid(SEQ / ABR, NHEAD, BATCH);      // (16, 16, 4)
    attn_tc<<<agrid, 256, ATTN_SMEM>>>(p_qh, p_kh16, p_vh16, p_attn16);

    // output projection (fp16 A from attn epilogue)
    mma_gemm<<<ggrid, 256, GEMM_SMEM>>>(p_attn16, p_w16o, bo, out, 0);
}

// round 9
// speedup vs baseline: 6.5884x; 1.1204x over previous
#include <cuda_runtime.h>
#include <cuda_fp16.h>
#include <cstdint>

#define D_MODEL 1024
#define NHEAD   16
#define DEPTH   64
#define SEQ     2048
#define BATCH   4
#define MROWS   (BATCH*SEQ)   // 8192

// ---------------- scratch (device globals; no allocs allowed) ----------------
__device__ __half g_q16[MROWS * D_MODEL];    // fp16 inputs (A operands)
__device__ __half g_k16[MROWS * D_MODEL];
__device__ __half g_v16[MROWS * D_MODEL];
__device__ __half g_w16q[D_MODEL * D_MODEL]; // W, k-pair-interleaved half2 [K/2][N]
__device__ __half g_w16k[D_MODEL * D_MODEL];
__device__ __half g_w16v[D_MODEL * D_MODEL];
__device__ __half g_w16o[D_MODEL * D_MODEL];
__device__ __half g_qh16[MROWS * D_MODEL];   // Q proj out, fp16 head-split [BH][S][D]
__device__ __half g_kh16[MROWS * D_MODEL];   // K proj out, fp16 head-split [BH][S][D]
__device__ __half g_vh16[MROWS * D_MODEL];   // V proj out, fp16 key-pair-interleaved [BH][S/2][D][2]
__device__ __half g_attn16[MROWS * D_MODEL]; // attn out, fp16 flat [B*S][D_MODEL]

// ---------------- helpers -----------------------------------------------------
__device__ __forceinline__ uint32_t smem_u32(const void* p) {
    return (uint32_t)__cvta_generic_to_shared(p);
}
__device__ __forceinline__ void cp_async16(uint32_t dst, const void* src) {
    asm volatile("cp.async.cg.shared.global [%0], [%1], 16;" :: "r"(dst), "l"(src));
}
__device__ __forceinline__ uint32_t pack_h2(float x, float y) {
    __half2 h = __floats2half2_rn(x, y);
    return *(uint32_t*)&h;
}
__device__ __forceinline__ void mma_f16(float* c, const uint32_t* a, const uint32_t* b) {
    asm volatile(
        "mma.sync.aligned.m16n8k16.row.col.f32.f16.f16.f32 "
        "{%0,%1,%2,%3},{%4,%5,%6,%7},{%8,%9},{%0,%1,%2,%3};"
        : "+f"(c[0]), "+f"(c[1]), "+f"(c[2]), "+f"(c[3])
        : "r"(a[0]), "r"(a[1]), "r"(a[2]), "r"(a[3]), "r"(b[0]), "r"(b[1]));
}

// ---------------- prep kernels (batched over blockIdx.y) -----------------------
__global__ void cvt_half3(const float* __restrict__ q, const float* __restrict__ k,
                          const float* __restrict__ v, __half* __restrict__ oq,
                          __half* __restrict__ ok, __half* __restrict__ ov)
{
    const float* X;  __half* Y;
    if      (blockIdx.y == 0) { X = q; Y = oq; }
    else if (blockIdx.y == 1) { X = k; Y = ok; }
    else                      { X = v; Y = ov; }
    const int i = (blockIdx.x * 256 + threadIdx.x) * 4;
    float4 f = *(const float4*)(X + i);
    __half2* Y2 = (__half2*)(Y + i);
    Y2[0] = __floats2half2_rn(f.x, f.y);
    Y2[1] = __floats2half2_rn(f.z, f.w);
}
// W [K][N] fp32 -> k-pair-interleaved half2: WH2[kp][n] = (W[2kp][n], W[2kp+1][n])
__global__ void wprep4(const float* __restrict__ wq, const float* __restrict__ wk,
                       const float* __restrict__ wv, const float* __restrict__ wo,
                       __half* __restrict__ oq, __half* __restrict__ ok,
                       __half* __restrict__ ov, __half* __restrict__ oo)
{
    const float* W;  __half* WH;
    if      (blockIdx.y == 0) { W = wq; WH = oq; }
    else if (blockIdx.y == 1) { W = wk; WH = ok; }
    else if (blockIdx.y == 2) { W = wv; WH = ov; }
    else                      { W = wo; WH = oo; }
    const int idx = blockIdx.x * 256 + threadIdx.x;
    const int kp = idx >> 8;
    const int n  = (idx & 255) * 4;
    float4 a = *(const float4*)(W + (size_t)(2 * kp) * D_MODEL + n);
    float4 b = *(const float4*)(W + (size_t)(2 * kp + 1) * D_MODEL + n);
    __half2* out = (__half2*)WH + (size_t)kp * D_MODEL + n;
    out[0] = __halves2half2(__float2half_rn(a.x), __float2half_rn(b.x));
    out[1] = __halves2half2(__float2half_rn(a.y), __float2half_rn(b.y));
    out[2] = __halves2half2(__float2half_rn(a.z), __float2half_rn(b.z));
    out[3] = __halves2half2(__float2half_rn(a.w), __float2half_rn(b.w));
}

// ---------------- fp16 mma.sync GEMM -------------------------------------------
// Y = A[M,1024] @ W[1024,1024] + bias.  A fp16 natural; W fp16 interleaved half2.
// mode 0: flat fp32; 2: head-split fp16; 3: head-split fp16 V-interleaved
#define AP2 20            // A pitch in half2 (40 halves = 80B)
#define BP2 136           // B pitch in half2 (544B)
#define A_STG_B 10240     // 128 * 80
#define B_STG_B 8704      // 16 * 544
#define A_STG_U 2560      // half2 units
#define B_STG_U 2176
#define GEMM_SMEM (2 * (A_STG_B + B_STG_B))   // 37888 B

__global__ __launch_bounds__(256, 2)
void mma_gemm(const __half* __restrict__ A, const __half* __restrict__ WH,
              const float* __restrict__ bias, void* __restrict__ Yv, int mode)
{
    extern __shared__ char smc[];
    uint32_t* AsU = (uint32_t*)smc;                       // [2][128][20] half2
    uint32_t* BsU = (uint32_t*)(smc + 2 * A_STG_B);       // [2][16][136] half2
    const uint32_t sA = smem_u32(AsU);
    const uint32_t sB = smem_u32(BsU);

    const int tid  = threadIdx.x;
    const int wid  = tid >> 5, lane = tid & 31;
    const int gid  = lane >> 2, tig = lane & 3;
    const int warp_m = wid & 1;
    const int warp_n = wid >> 1;
    const int m0 = blockIdx.y * 128;
    const int n0 = blockIdx.x * 128;

    float acc[4][4][4];
#pragma unroll
    for (int mi = 0; mi < 4; mi++)
#pragma unroll
        for (int ni = 0; ni < 4; ni++)
#pragma unroll
            for (int r = 0; r < 4; r++) acc[mi][ni][r] = 0.f;

    auto fill = [&](int kt) {
        const int buf = kt & 1;
        const uint32_t dA = sA + buf * A_STG_B;
        const uint32_t dB = sB + buf * B_STG_B;
        const __half* gA = A + (size_t)m0 * D_MODEL + kt * 32;
        const uint32_t* gB = (const uint32_t*)WH + (size_t)(kt * 16) * D_MODEL + n0;
#pragma unroll
        for (int i = 0; i < 2; i++) {
            const int f = i * 256 + tid;
            const int ra = f >> 2, ca = (f & 3) * 8;            // A: 128 rows x 4 chunks
            cp_async16(dA + ra * 80 + ca * 2, gA + (size_t)ra * D_MODEL + ca);
            const int rb = f >> 5, cb = (f & 31) * 4;           // B: 16 rows x 32 chunks
            cp_async16(dB + rb * 544 + cb * 4, gB + (size_t)rb * D_MODEL + cb);
        }
        asm volatile("cp.async.commit_group;");
    };

    auto compute = [&](int kt) {
        const int buf = kt & 1;
        const uint32_t* a_s = AsU + buf * A_STG_U;
        const uint32_t* b_s = BsU + buf * B_STG_U;
#pragma unroll
        for (int ks = 0; ks < 2; ks++) {
            const int k8 = ks * 8;
            uint32_t af[4][4], bf[4][2];
#pragma unroll
            for (int mi = 0; mi < 4; mi++) {
                const int r = warp_m * 64 + mi * 16 + gid;
                af[mi][0] = a_s[r * AP2 + k8 + tig];
                af[mi][1] = a_s[(r + 8) * AP2 + k8 + tig];
                af[mi][2] = a_s[r * AP2 + k8 + tig + 4];
                af[mi][3] = a_s[(r + 8) * AP2 + k8 + tig + 4];
            }
#pragma unroll
            for (int ni = 0; ni < 4; ni++) {
                const int c = warp_n * 32 + ni * 8 + gid;
                bf[ni][0] = b_s[(k8 + tig) * BP2 + c];
                bf[ni][1] = b_s[(k8 + tig + 4) * BP2 + c];
            }
#pragma unroll
            for (int mi = 0; mi < 4; mi++)
#pragma unroll
                for (int ni = 0; ni < 4; ni++)
                    mma_f16(acc[mi][ni], af[mi], bf[ni]);
        }
    };

    fill(0);
    fill(1);
    asm volatile("cp.async.wait_group 1;");
    __syncthreads();

#pragma unroll 1
    for (int kt = 0; kt < 32; kt++) {
        compute(kt);
        __syncthreads();
        if (kt + 2 < 32) {
            fill(kt + 2);
            asm volatile("cp.async.wait_group 1;");
        } else {
            asm volatile("cp.async.wait_group 0;");
        }
        __syncthreads();
    }

#pragma unroll
    for (int mi = 0; mi < 4; mi++) {
        const int r = m0 + warp_m * 64 + mi * 16 + gid;
#pragma unroll
        for (int ni = 0; ni < 4; ni++) {
            const int n = n0 + warp_n * 32 + ni * 8 + 2 * tig;
            const float bv0 = bias[n], bv1 = bias[n + 1];
            float2 lo, hi;
            lo.x = acc[mi][ni][0] + bv0; lo.y = acc[mi][ni][1] + bv1;
            hi.x = acc[mi][ni][2] + bv0; hi.y = acc[mi][ni][3] + bv1;
            if (mode == 0) {
                float* Y = (float*)Yv;
                *(float2*)&Y[(size_t)r * D_MODEL + n] = lo;
                *(float2*)&Y[(size_t)(r + 8) * D_MODEL + n] = hi;
            } else {
                const int h = n >> 6, d = n & 63;
                const int b0 = r >> 11, s0 = r & (SEQ - 1);
                const int bh = b0 * NHEAD + h;
                const int s1 = ((r + 8) & (SEQ - 1));
                if (mode == 2) {
                    __half2* Y = (__half2*)Yv;
                    Y[(size_t)(bh * SEQ + s0) * (DEPTH / 2) + (d >> 1)] = __floats2half2_rn(lo.x, lo.y);
                    Y[(size_t)(bh * SEQ + s1) * (DEPTH / 2) + (d >> 1)] = __floats2half2_rn(hi.x, hi.y);
                } else {   // mode 3: V key-pair interleaved
                    __half* Y = (__half*)Yv;
                    size_t i0 = (((size_t)bh * (SEQ / 2) + (s0 >> 1)) * DEPTH + d) * 2 + (s0 & 1);
                    size_t i1 = (((size_t)bh * (SEQ / 2) + (s1 >> 1)) * DEPTH + d) * 2 + (s1 & 1);
                    Y[i0]     = __float2half_rn(lo.x);
                    Y[i0 + 2] = __float2half_rn(lo.y);
                    Y[i1]     = __float2half_rn(hi.x);
                    Y[i1 + 2] = __float2half_rn(hi.y);
                }
            }
        }
    }
}

// ---------------- fp16 tensor-core flash attention -----------------------------
// grid (SEQ/128, NHEAD, BATCH), 256 thr. Q/K/V all fp16 from projections.
// 1/sqrt(depth) applied exactly to S (fp32) after the QK MMA.
#define ABR 128
#define ABC 32
#define QP2 36   // q pitch, half2 (32 used + 4 pad; row = 64 halves = 128B)
#define KP2 36   // k pitch, half2
#define VP2 72   // v pitch, half2 (64 used + 8 pad; pair-row = 128 halves = 256B)
#define Q_STG_U (128 * QP2)        // 4608 half2
#define K_STG_U (32 * KP2)         // 1152
#define V_STG_U (16 * VP2)         // 1152
#define K_STG_B (K_STG_U * 4)
#define V_STG_B (V_STG_U * 4)
#define ATTN_SMEM ((Q_STG_U + 2 * K_STG_U + 2 * V_STG_U) * 4)   // 36864 B

__global__ __launch_bounds__(256, 2)
void attn_tc(const __half* __restrict__ Qh, const __half* __restrict__ Kh,
             const __half* __restrict__ Vh, __half* __restrict__ O)
{
    extern __shared__ char smc[];
    uint32_t* qsm = (uint32_t*)smc;                    // [128][36]
    uint32_t* ksm = qsm + Q_STG_U;                     // [2][32][36]
    uint32_t* vsm = ksm + 2 * K_STG_U;                 // [2][16][72]
    const uint32_t sQ = smem_u32(qsm);
    const uint32_t sK = smem_u32(ksm);
    const uint32_t sV = smem_u32(vsm);

    const int qt = blockIdx.x;
    const int h  = blockIdx.y;
    const int b  = blockIdx.z;
    const int tid = threadIdx.x;
    const int w = tid >> 5, lane = tid & 31;
    const int gid = lane >> 2, tig = lane & 3;
    const int bh = b * NHEAD + h;

    const __half*   Qb  = Qh + (size_t)(bh * SEQ + qt * ABR) * DEPTH;
    const __half*   Kb  = Kh + (size_t)(bh * SEQ) * DEPTH;
    const uint32_t* Vb2 = (const uint32_t*)Vh + (size_t)bh * (SEQ / 2) * DEPTH;

    // load Q tile: 128 rows x 128B via cp.async (1024 chunks, 4/thread)
#pragma unroll
    for (int i = 0; i < 4; i++) {
        const int f = i * 256 + tid;
        const int r = f >> 3, c = (f & 7) * 8;   // c in halves
        cp_async16(sQ + r * (QP2 * 4) + c * 2, Qb + (size_t)r * DEPTH + c);
    }

    auto fill = [&](int kt) {
        const int buf = kt & 1;
        {   // K tile: 32 rows x 128B
            const int r = tid >> 3, c = (tid & 7) * 8;
            const __half* gK = Kb + (size_t)(kt * ABC) * DEPTH;
            cp_async16(sK + buf * K_STG_B + r * (KP2 * 4) + c * 2, gK + (size_t)r * DEPTH + c);
        }
        {   // V tile: 16 pair-rows x 256B
            const int rp = tid >> 4, c4 = (tid & 15) * 4;
            const uint32_t* gV = Vb2 + (size_t)(kt * 16) * DEPTH;
            cp_async16(sV + buf * V_STG_B + rp * (VP2 * 4) + c4 * 4, gV + (size_t)rp * DEPTH + c4);
        }
        asm volatile("cp.async.commit_group;");
    };

    float m0 = -1e30f, m1 = -1e30f, l0 = 0.f, l1 = 0.f;
    float o[8][4];
#pragma unroll
    for (int nt = 0; nt < 8; nt++)
#pragma unroll
        for (int r = 0; r < 4; r++) o[nt][r] = 0.f;

    fill(0);
    asm volatile("cp.async.wait_group 0;");
    __syncthreads();

#pragma unroll 1
    for (int kt = 0; kt < SEQ / ABC; kt++) {
        if (kt + 1 < SEQ / ABC) fill(kt + 1);

        const uint32_t* ks_ = ksm + (kt & 1) * K_STG_U;
        const uint32_t* vs_ = vsm + (kt & 1) * V_STG_U;

        // ---- S = Q K^T (both fp16), then exact fp32 scale ----
        float s[4][4];
#pragma unroll
        for (int nt = 0; nt < 4; nt++)
#pragma unroll
            for (int r = 0; r < 4; r++) s[nt][r] = 0.f;

        const int qr = 16 * w + gid;
#pragma unroll
        for (int ks = 0; ks < 4; ks++) {
            const int k8 = ks * 8;
            uint32_t aq[4];
            aq[0] = qsm[qr * QP2 + k8 + tig];
            aq[1] = qsm[(qr + 8) * QP2 + k8 + tig];
            aq[2] = qsm[qr * QP2 + k8 + tig + 4];
            aq[3] = qsm[(qr + 8) * QP2 + k8 + tig + 4];
#pragma unroll
            for (int nt = 0; nt < 4; nt++) {
                uint32_t bh2[2];
                const int key = 8 * nt + gid;
                bh2[0] = ks_[key * KP2 + k8 + tig];
                bh2[1] = ks_[key * KP2 + k8 + tig + 4];
                mma_f16(s[nt], aq, bh2);
            }
        }
#pragma unroll
        for (int nt = 0; nt < 4; nt++) {
            s[nt][0] *= 0.125f; s[nt][1] *= 0.125f;
            s[nt][2] *= 0.125f; s[nt][3] *= 0.125f;
        }

        // ---- online softmax ----
        float smax0 = -1e30f, smax1 = -1e30f;
#pragma unroll
        for (int nt = 0; nt < 4; nt++) {
            smax0 = fmaxf(smax0, fmaxf(s[nt][0], s[nt][1]));
            smax1 = fmaxf(smax1, fmaxf(s[nt][2], s[nt][3]));
        }
#pragma unroll
        for (int off = 1; off <= 2; off <<= 1) {
            smax0 = fmaxf(smax0, __shfl_xor_sync(0xffffffffu, smax0, off));
            smax1 = fmaxf(smax1, __shfl_xor_sync(0xffffffffu, smax1, off));
        }
        const float mn0 = fmaxf(m0, smax0), mn1 = fmaxf(m1, smax1);
        const float cr0 = __expf(m0 - mn0), cr1 = __expf(m1 - mn1);
        float sum0 = 0.f, sum1 = 0.f;
#pragma unroll
        for (int nt = 0; nt < 4; nt++) {
            s[nt][0] = __expf(s[nt][0] - mn0);
            s[nt][1] = __expf(s[nt][1] - mn0);
            s[nt][2] = __expf(s[nt][2] - mn1);
            s[nt][3] = __expf(s[nt][3] - mn1);
            sum0 += s[nt][0] + s[nt][1];
            sum1 += s[nt][2] + s[nt][3];
        }
#pragma unroll
        for (int off = 1; off <= 2; off <<= 1) {
            sum0 += __shfl_xor_sync(0xffffffffu, sum0, off);
            sum1 += __shfl_xor_sync(0xffffffffu, sum1, off);
        }
        l0 = l0 * cr0 + sum0; l1 = l1 * cr1 + sum1;
        m0 = mn0; m1 = mn1;
#pragma unroll
        for (int nt = 0; nt < 8; nt++) {
            o[nt][0] *= cr0; o[nt][1] *= cr0;
            o[nt][2] *= cr1; o[nt][3] *= cr1;
        }

        // ---- O += P V : QK C-fragments ARE PV A-fragments (fp16 k16) ----
#pragma unroll
        for (int kc = 0; kc < 2; kc++) {
            uint32_t ap[4];
            ap[0] = pack_h2(s[2 * kc][0],     s[2 * kc][1]);
            ap[1] = pack_h2(s[2 * kc][2],     s[2 * kc][3]);
            ap[2] = pack_h2(s[2 * kc + 1][0], s[2 * kc + 1][1]);
            ap[3] = pack_h2(s[2 * kc + 1][2], s[2 * kc + 1][3]);
#pragma unroll
            for (int nt = 0; nt < 8; nt++) {
                uint32_t bv[2];
                const int d = 8 * nt + gid;
                bv[0] = vs_[(kc * 8 + tig) * VP2 + d];
                bv[1] = vs_[(kc * 8 + tig + 4) * VP2 + d];
                mma_f16(o[nt], ap, bv);
            }
        }
        // next tile must be resident; also orders buffer reuse
        if (kt + 1 < SEQ / ABC) asm volatile("cp.async.wait_group 0;");
        __syncthreads();
    }

    // epilogue: normalize, fp16, write flat [B*S][D_MODEL]
    const float inv0 = 1.f / l0, inv1 = 1.f / l1;
    const int r0 = qt * ABR + 16 * w + gid;
    const int r1 = r0 + 8;
    uint32_t* O2 = (uint32_t*)O;
#pragma unroll
    for (int nt = 0; nt < 8; nt++) {
        const int d = h * DEPTH + 8 * nt + 2 * tig;
        O2[((size_t)(b * SEQ + r0) * D_MODEL + d) >> 1] = pack_h2(o[nt][0] * inv0, o[nt][1] * inv0);
        O2[((size_t)(b * SEQ + r1) * D_MODEL + d) >> 1] = pack_h2(o[nt][2] * inv1, o[nt][3] * inv1);
    }
}

// ---------------- launch -------------------------------------------------------
extern "C" void kernel_launch(void* const* d_in, const int* in_sizes, int n_in,
                              void* d_out, int out_size)
{
    const float* v  = (const float*)d_in[0];
    const float* k  = (const float*)d_in[1];
    const float* q  = (const float*)d_in[2];
    const float* wq = (const float*)d_in[3];
    const float* bq = (const float*)d_in[4];
    const float* wk = (const float*)d_in[5];
    const float* bk = (const float*)d_in[6];
    const float* wv = (const float*)d_in[7];
    const float* bv = (const float*)d_in[8];
    const float* wo = (const float*)d_in[9];
    const float* bo = (const float*)d_in[10];
    float* out = (float*)d_out;

    __half *p_q16, *p_k16, *p_v16, *p_w16q, *p_w16k, *p_w16v, *p_w16o;
    __half *p_qh16, *p_kh16, *p_vh16, *p_attn16;
    cudaGetSymbolAddress((void**)&p_q16,   g_q16);
    cudaGetSymbolAddress((void**)&p_k16,   g_k16);
    cudaGetSymbolAddress((void**)&p_v16,   g_v16);
    cudaGetSymbolAddress((void**)&p_w16q,  g_w16q);
    cudaGetSymbolAddress((void**)&p_w16k,  g_w16k);
    cudaGetSymbolAddress((void**)&p_w16v,  g_w16v);
    cudaGetSymbolAddress((void**)&p_w16o,  g_w16o);
    cudaGetSymbolAddress((void**)&p_qh16,  g_qh16);
    cudaGetSymbolAddress((void**)&p_kh16,  g_kh16);
    cudaGetSymbolAddress((void**)&p_vh16,  g_vh16);
    cudaGetSymbolAddress((void**)&p_attn16, g_attn16);

    cudaFuncSetAttribute(mma_gemm, cudaFuncAttributeMaxDynamicSharedMemorySize, GEMM_SMEM);
    cudaFuncSetAttribute(attn_tc,  cudaFuncAttributeMaxDynamicSharedMemorySize, ATTN_SMEM);

    // prep: fused conversions (2 launches)
    dim3 cgrid((MROWS * D_MODEL) / (256 * 4), 3);
    cvt_half3<<<cgrid, 256>>>(q, k, v, p_q16, p_k16, p_v16);
    dim3 wgrid((D_MODEL / 2) * (D_MODEL / 4) / 256, 4);
    wprep4<<<wgrid, 256>>>(wq, wk, wv, wo, p_w16q, p_w16k, p_w16v, p_w16o);

    // projections (fp16 tensor)
    dim3 ggrid(D_MODEL / 128, MROWS / 128);   // (8, 64)
    mma_gemm<<<ggrid, 256, GEMM_SMEM>>>(p_q16, p_w16q, bq, p_qh16, 2);  // Q: fp16 head-split
    mma_gemm<<<ggrid, 256, GEMM_SMEM>>>(p_k16, p_w16k, bk, p_kh16, 2);  // K: fp16 head-split
    mma_gemm<<<ggrid, 256, GEMM_SMEM>>>(p_v16, p_w16v, bv, p_vh16, 3);  // V: fp16 interleaved

    // attention (fp16 tensor, flash)
    dim3 agrid(SEQ / ABR, NHEAD, BATCH);      // (16, 16, 4)
    attn_tc<<<agrid, 256, ATTN_SMEM>>>(p_qh16, p_kh16, p_vh16, p_attn16);

    // output projection (fp16 A from attn epilogue)
    mma_gemm<<<ggrid, 256, GEMM_SMEM>>>(p_attn16, p_w16o, bo, out, 0);
}